// round 10
// baseline (speedup 1.0000x reference)
#include <cuda_runtime.h>
#include <cuda_bf16.h>
#include <math.h>
#include <cstdint>

#define N_UD   500000
#define N_USER 4000
#define N_SUP  300
#define H      128
#define HH     (H*H)
#define E_BIG  500000
#define E_SMALL 4000
#define SZ_U   (N_USER*H)
#define SZ_S   (N_SUP*H)
#define NA     (N_UD + N_USER)   // combined CSR key space
#define NBLK   493               // ceil(NA/1024)
#define N_TILES 3907             // ceil(N_UD/128)

// ---------------- scratch (static __device__ -> no allocations) ----------------
__device__ __align__(16) float g_hud0[(size_t)N_UD*H];
__device__ __align__(16) float g_hud1[(size_t)N_UD*H];
__device__ __align__(16) float g_user0[SZ_U];
__device__ __align__(16) float g_user1[SZ_U];
__device__ __align__(16) float g_sup0[SZ_S];
__device__ __align__(16) float g_sup1[SZ_S];
__device__ __align__(16) float g_tuser[SZ_U];

// bf16-split, transposed weights for the two big GEMMs: B[n][k] = W[k][n]
__device__ __align__(16) __nv_bfloat16 g_Bhi[2*HH];
__device__ __align__(16) __nv_bfloat16 g_Blo[2*HH];

// combined CSR: keys [0,N_UD) = e1 by dst (vals = e1 src user)
//               keys [N_UD,NA) = e0 by dst user (vals = e0 src UD)
__device__ int g_cnt[NA];
__device__ int g_rowptr[NA];
__device__ int g_pos[NA];
__device__ int g_csrc[2*E_BIG];
__device__ int g_bsum[NBLK];
__device__ int g_boff[NBLK];

#define AGG_TOT (2*(2*SZ_U+SZ_S))
__device__ __align__(16) float g_agg[AGG_TOT];
#define L1_UB 0
#define L1_US (SZ_U)
#define L1_S  (2*SZ_U)
#define L2_UB (2*SZ_U+SZ_S)
#define L2_US (L2_UB+SZ_U)
#define L2_S  (L2_UB+2*SZ_U)

// ---------------- helpers ----------------
__device__ __forceinline__ uint32_t smem_to_u32(const void* p) {
    uint32_t a;
    asm("{ .reg .u64 t; cvta.to.shared.u64 t, %1; cvt.u32.u64 %0, t; }" : "=r"(a) : "l"(p));
    return a;
}
__device__ __forceinline__ void red_add_v4(float* p, float4 v) {
    asm volatile("red.global.add.v4.f32 [%0], {%1,%2,%3,%4};"
                 :: "l"(p), "f"(v.x), "f"(v.y), "f"(v.z), "f"(v.w) : "memory");
}
__device__ __forceinline__ void ldsm_x4(uint32_t* r, uint32_t addr) {
    asm volatile("ldmatrix.sync.aligned.m8n8.x4.shared.b16 {%0,%1,%2,%3}, [%4];"
        : "=r"(r[0]), "=r"(r[1]), "=r"(r[2]), "=r"(r[3]) : "r"(addr));
}
__device__ __forceinline__ void mma_bf16(float* d, const uint32_t* a, const uint32_t* b) {
    asm volatile("mma.sync.aligned.m16n8k16.row.col.f32.bf16.bf16.f32 "
        "{%0,%1,%2,%3}, {%4,%5,%6,%7}, {%8,%9}, {%0,%1,%2,%3};"
        : "+f"(d[0]), "+f"(d[1]), "+f"(d[2]), "+f"(d[3])
        : "r"(a[0]), "r"(a[1]), "r"(a[2]), "r"(a[3]), "r"(b[0]), "r"(b[1]));
}

// ---------------- zero kernels ----------------
__global__ void k_zero_agg() {
    int g = blockIdx.x * blockDim.x + threadIdx.x;
    float4* p = (float4*)g_agg;
    if (g < AGG_TOT/4) p[g] = make_float4(0.f,0.f,0.f,0.f);
}
__global__ void k_zero_cnt() {
    int g = blockIdx.x * blockDim.x + threadIdx.x;
    if (g < NA/4) ((int4*)g_cnt)[g] = make_int4(0,0,0,0);
}

// ---------------- combined CSR build ----------------
__global__ void k_hist2(const int* __restrict__ e1d, const int* __restrict__ e0d) {
    int e = blockIdx.x * blockDim.x + threadIdx.x;
    if (e < E_BIG) {
        atomicAdd(&g_cnt[e1d[e]], 1);
        atomicAdd(&g_cnt[N_UD + e0d[e]], 1);
    }
}
__global__ void k_bsum() {
    __shared__ int s[256];
    int b = blockIdx.x, t = threadIdx.x;
    int sum = 0;
    for (int i = t; i < 1024; i += 256) {
        int idx = b*1024 + i;
        if (idx < NA) sum += g_cnt[idx];
    }
    s[t] = sum; __syncthreads();
    for (int o = 128; o > 0; o >>= 1) { if (t < o) s[t] += s[t+o]; __syncthreads(); }
    if (t == 0) g_bsum[b] = s[0];
}
__global__ void k_scan_top() {
    __shared__ int s[512];
    int t = threadIdx.x;
    int v = (t < NBLK) ? g_bsum[t] : 0;
    s[t] = v; __syncthreads();
    for (int o = 1; o < 512; o <<= 1) {
        int x = (t >= o) ? s[t-o] : 0;
        __syncthreads(); s[t] += x; __syncthreads();
    }
    if (t < NBLK) g_boff[t] = s[t] - v;
}
__global__ void k_scan_write() {
    __shared__ int s[1024];
    int b = blockIdx.x, t = threadIdx.x;
    int idx = b*1024 + t;
    int v = (idx < NA) ? g_cnt[idx] : 0;
    s[t] = v; __syncthreads();
    for (int o = 1; o < 1024; o <<= 1) {
        int x = (t >= o) ? s[t-o] : 0;
        __syncthreads(); s[t] += x; __syncthreads();
    }
    if (idx < NA) {
        int r = g_boff[b] + s[t] - v;
        g_rowptr[idx] = r;
        g_pos[idx] = r;
    }
}
__global__ void k_fill2(const int* __restrict__ e1s, const int* __restrict__ e1d,
                        const int* __restrict__ e0s, const int* __restrict__ e0d) {
    int e = blockIdx.x * blockDim.x + threadIdx.x;
    if (e >= E_BIG) return;
    int p = atomicAdd(&g_pos[e1d[e]], 1);
    g_csrc[p] = e1s[e];
    int q = atomicAdd(&g_pos[N_UD + e0d[e]], 1);
    g_csrc[q] = e0s[e];
}

// ---------------- weight prep: transpose + bf16 split ----------------
__global__ void k_prepW(const float* __restrict__ W0, const float* __restrict__ W1) {
    int i = blockIdx.x * blockDim.x + threadIdx.x;
    if (i >= 2*HH) return;
    int w = i >> 14;
    int r = i & (HH-1);
    int n = r >> 7, k = r & 127;
    const float* W = w ? W1 : W0;
    float v = W[k*H + n];
    __nv_bfloat16 hi = __float2bfloat16(v);
    float hf = __bfloat162float(hi);
    g_Bhi[i] = hi;
    g_Blo[i] = __float2bfloat16(v - hf);
}

// ---------------- gather embedding rows via nid ----------------
__global__ void k_gather_rows(const float* __restrict__ emb, const int* __restrict__ nid,
                              float* __restrict__ out, int M) {
    int g = blockIdx.x * blockDim.x + threadIdx.x;
    int row = g >> 5, lane = g & 31;
    if (row >= M) return;
    int r = nid[row];
    float4 v = *(const float4*)(emb + (size_t)r*H + lane*4);
    *(float4*)(out + (size_t)row*H + lane*4) = v;
}

// ---------------- edge scatter-add (small edge sets only) ----------------
template<bool RELU>
__global__ void k_edge_add(const float* __restrict__ src_tab, const int* __restrict__ es,
                           const int* __restrict__ ed, float* __restrict__ dst_tab, int E) {
    int g = blockIdx.x * blockDim.x + threadIdx.x;
    int e = g >> 5;
    if (e >= E) return;
    int lane = g & 31;
    int s = es[e], d = ed[e];
    float4 v = *(const float4*)(src_tab + (size_t)s*H + lane*4);
    if (RELU) { v.x=fmaxf(v.x,0.f); v.y=fmaxf(v.y,0.f); v.z=fmaxf(v.z,0.f); v.w=fmaxf(v.w,0.f); }
    red_add_v4(dst_tab + (size_t)d*H + lane*4, v);
}

// ---------------- e0 aggregation by gather: one CTA per user row ----------------
template<bool RELU>
__global__ __launch_bounds__(128)
void k_agg_user(const float* __restrict__ hud, const int* __restrict__ rowptr,
                const int* __restrict__ csrc, float* __restrict__ aggUB) {
    int u = blockIdx.x;
    int tid = threadIdx.x;
    int beg = rowptr[N_UD + u];
    int end = (u == N_USER-1) ? 2*E_BIG : rowptr[N_UD + u + 1];
    float acc = 0.f;
    int e = beg;
    for (; e + 4 <= end; e += 4) {
        int s0 = csrc[e], s1 = csrc[e+1], s2 = csrc[e+2], s3 = csrc[e+3];
        float v0 = hud[(size_t)s0*H + tid];
        float v1 = hud[(size_t)s1*H + tid];
        float v2 = hud[(size_t)s2*H + tid];
        float v3 = hud[(size_t)s3*H + tid];
        if (RELU) {
            v0 = fmaxf(v0, 0.f); v1 = fmaxf(v1, 0.f);
            v2 = fmaxf(v2, 0.f); v3 = fmaxf(v3, 0.f);
        }
        acc += (v0 + v1) + (v2 + v3);
    }
    for (; e < end; ++e) {
        float v = hud[(size_t)csrc[e]*H + tid];
        if (RELU) v = fmaxf(v, 0.f);
        acc += v;
    }
    aggUB[(size_t)u*H + tid] = acc;
}

// ---------------- small GEMM ----------------
__global__ void k_gemm_small(const float* __restrict__ A, const float* __restrict__ W,
                             const float* __restrict__ bias, float* __restrict__ C,
                             int M, int accum, int relu) {
    int g = blockIdx.x * blockDim.x + threadIdx.x;
    int row = g >> 5;
    if (row >= M) return;
    int lane = g & 31;
    const float* a = A + (size_t)row*H;
    float4 acc = make_float4(0.f,0.f,0.f,0.f);
    #pragma unroll 8
    for (int k = 0; k < H; ++k) {
        float av = __ldg(a + k);
        float4 w = *(const float4*)(W + (size_t)k*H + lane*4);
        acc.x += av*w.x; acc.y += av*w.y; acc.z += av*w.z; acc.w += av*w.w;
    }
    if (bias) {
        float4 b = *(const float4*)(bias + lane*4);
        acc.x += b.x; acc.y += b.y; acc.z += b.z; acc.w += b.w;
    }
    float* cp = C + (size_t)row*H + lane*4;
    if (accum) {
        float4 old = *(float4*)cp;
        acc.x += old.x; acc.y += old.y; acc.z += old.z; acc.w += old.w;
    }
    if (relu) { acc.x=fmaxf(acc.x,0.f); acc.y=fmaxf(acc.y,0.f); acc.z=fmaxf(acc.z,0.f); acc.w=fmaxf(acc.w,0.f); }
    *(float4*)cp = acc;
}

// ================= fused big GEMM, half-K A staging, 2 CTAs/SM =================
// MODE 1: A = feat(x_ud,Wf,bf,emb[nid]) (side-writes hud0); C = A@W + b + e1-CSR(tuser)
// MODE 2: A = relu(Ain); C = A@W + b + e1-CSR(tuser); pred = log_softmax(C@Wout + bout)
// D = Ahi*Bhi + Ahi*Blo + Alo*Bhi, fp32 accumulators in registers.
#define PADB     272        // B row pitch (128 bf16 + pad)
#define PADA     144        // A row pitch (64 bf16 + pad), half-K staging
#define SM_W     0          // 128*272 = 34816
#define SM_WLO   34816      // -> 69632
#define SM_A     69632      // 128*144 = 18432
#define SM_ALO   88064      // -> 106496
#define SM_BIAS  106496     // 512 B
#define SM_EX    107008     // 3072 B
#define TC_SMEM  110080
#define SM_STAGE SM_A       // epilogue stage overlays A (36864 B >= 64*132*4)
#define STG_STRIDE 132

template<int MODE>
__global__ __launch_bounds__(256, 2)
void k_fused_mma(const float* __restrict__ bias,
                 const float* __restrict__ tuser, const int* __restrict__ rowptr,
                 const int* __restrict__ csrc, float* __restrict__ C,
                 const float* __restrict__ Ain,
                 const float* __restrict__ xud, const int* __restrict__ nid,
                 const float* __restrict__ emb, const float* __restrict__ Wf,
                 const float* __restrict__ bf, float* __restrict__ hud0,
                 const float* __restrict__ Wout, const float* __restrict__ bout,
                 float* __restrict__ pred, const __nv_bfloat16* __restrict__ Bh,
                 const __nv_bfloat16* __restrict__ Bl, int M) {
    extern __shared__ char smem[];
    uint32_t smem_base = smem_to_u32(smem);
    float* sBias = (float*)(smem + SM_BIAS);
    float* sEx   = (float*)(smem + SM_EX);

    int tid  = threadIdx.x;
    int wid  = tid >> 5;
    int lane = tid & 31;
    long blockRow = (long)blockIdx.x * 128;

    if (tid < 128) sBias[tid] = bias[tid];
    if (MODE == 1) {
        for (int i = tid; i < 768; i += 256) sEx[i] = (i < 640) ? Wf[i] : bf[i-640];
    } else {
        if (tid < 256) sEx[tid] = Wout[tid];
    }
    for (int i = tid; i < 2048; i += 256) {
        uint4 vh = ((const uint4*)Bh)[i];
        uint4 vl = ((const uint4*)Bl)[i];
        int n  = i >> 4;
        int kq = i & 15;
        int dst = n*PADB + kq*16;
        *(uint4*)(smem + SM_W   + dst) = vh;
        *(uint4*)(smem + SM_WLO + dst) = vl;
    }

    // prologue thread mapping: 2 threads/row, each 32 cols of the current K-half
    int prow = tid & 127;
    int kq2  = tid >> 7;                   // 0..1
    long rowReal = blockRow + prow;
    bool rok = rowReal < M;
    long rsrc = rok ? rowReal : (M-1);
    float x0=0,x1=0,x2=0,x3=0,x4=0; long nr = 0;
    if (MODE == 1) {
        nr = nid[rsrc];
        const float* xp = xud + rsrc*5;
        x0=xp[0]; x1=xp[1]; x2=xp[2]; x3=xp[3]; x4=xp[4];
    }
    __syncthreads();    // W + sEx visible

    // MMA layout: 8 warps, warp (wm, wn) owns 32 rows x 64 cols
    int wm = wid & 3, wn = wid >> 2;
    float acc[2][8][4];
    #pragma unroll
    for (int mt = 0; mt < 2; ++mt)
        #pragma unroll
        for (int nt = 0; nt < 8; ++nt)
            #pragma unroll
            for (int q = 0; q < 4; ++q) acc[mt][nt][q] = 0.f;

    for (int half = 0; half < 2; ++half) {
        // ---- prologue: build 128x64 A half-tile, bf16 hi/lo -> smem ----
        #pragma unroll
        for (int j = 0; j < 8; ++j) {
            int klocal = kq2*32 + j*4;          // 0..63 within half
            int k = half*64 + klocal;
            float4 o;
            if (MODE == 1) {
                float4 e  = *(const float4*)(emb + nr*H + k);
                float4 w0 = *(const float4*)(sEx + 0*H + k);
                float4 w1 = *(const float4*)(sEx + 1*H + k);
                float4 w2 = *(const float4*)(sEx + 2*H + k);
                float4 w3 = *(const float4*)(sEx + 3*H + k);
                float4 w4 = *(const float4*)(sEx + 4*H + k);
                float4 bb = *(const float4*)(sEx + 5*H + k);
                o.x = bb.x + e.x + x0*w0.x + x1*w1.x + x2*w2.x + x3*w3.x + x4*w4.x;
                o.y = bb.y + e.y + x0*w0.y + x1*w1.y + x2*w2.y + x3*w3.y + x4*w4.y;
                o.z = bb.z + e.z + x0*w0.z + x1*w1.z + x2*w2.z + x3*w3.z + x4*w4.z;
                o.w = bb.w + e.w + x0*w0.w + x1*w1.w + x2*w2.w + x3*w3.w + x4*w4.w;
                if (rok) *(float4*)(hud0 + rowReal*H + k) = o;
            } else {
                o = *(const float4*)(Ain + rsrc*H + k);
                o.x=fmaxf(o.x,0.f); o.y=fmaxf(o.y,0.f); o.z=fmaxf(o.z,0.f); o.w=fmaxf(o.w,0.f);
            }
            uint32_t h0, h1;
            asm("cvt.rn.bf16x2.f32 %0, %1, %2;" : "=r"(h0) : "f"(o.y), "f"(o.x));
            asm("cvt.rn.bf16x2.f32 %0, %1, %2;" : "=r"(h1) : "f"(o.w), "f"(o.z));
            float hx = __uint_as_float(h0 << 16);
            float hy = __uint_as_float(h0 & 0xffff0000u);
            float hz = __uint_as_float(h1 << 16);
            float hw = __uint_as_float(h1 & 0xffff0000u);
            uint32_t l0, l1;
            asm("cvt.rn.bf16x2.f32 %0, %1, %2;" : "=r"(l0) : "f"(o.y - hy), "f"(o.x - hx));
            asm("cvt.rn.bf16x2.f32 %0, %1, %2;" : "=r"(l1) : "f"(o.w - hw), "f"(o.z - hz));
            uint2 hh; hh.x = h0; hh.y = h1;
            uint2 ll; ll.x = l0; ll.y = l1;
            int off = prow*PADA + klocal*2;
            *(uint2*)(smem + SM_A   + off) = hh;
            *(uint2*)(smem + SM_ALO + off) = ll;
        }
        __syncthreads();

        // ---- MMA over this K half (register-lean B loads) ----
        #pragma unroll
        for (int kcl = 0; kcl < 4; ++kcl) {
            int kg = half*4 + kcl;
            uint32_t ah[2][4], al[2][4];
            #pragma unroll
            for (int mt = 0; mt < 2; ++mt) {
                int row  = wm*32 + mt*16 + (lane & 15);
                int koff = kcl*16 + (lane >> 4)*8;      // within half
                uint32_t off = row*PADA + koff*2;
                ldsm_x4(ah[mt], smem_base + SM_A   + off);
                ldsm_x4(al[mt], smem_base + SM_ALO + off);
            }
            #pragma unroll
            for (int g = 0; g < 4; ++g) {
                uint32_t bh[4], bl[4];
                int n    = wn*64 + g*16 + (lane & 7) + (lane >> 4)*8;
                int koff = kg*16 + ((lane >> 3) & 1)*8; // full-K index into W
                uint32_t off = n*PADB + koff*2;
                ldsm_x4(bh, smem_base + SM_W   + off);
                ldsm_x4(bl, smem_base + SM_WLO + off);
                #pragma unroll
                for (int mt = 0; mt < 2; ++mt) {
                    #pragma unroll
                    for (int h = 0; h < 2; ++h) {
                        int nt = 2*g + h;
                        const uint32_t* bph = bh + h*2;
                        const uint32_t* bpl = bl + h*2;
                        mma_bf16(acc[mt][nt], ah[mt], bph);
                        mma_bf16(acc[mt][nt], ah[mt], bpl);
                        mma_bf16(acc[mt][nt], al[mt], bph);
                    }
                }
            }
        }
        __syncthreads();   // A half consumed; safe to overwrite / stage
    }

    // ---- epilogue in two 64-row passes (stage overlays A region) ----
    float* stage = (float*)(smem + SM_STAGE);
    float bo0 = 0.f, bo1 = 0.f;
    if (MODE == 2) { bo0 = bout[0]; bo1 = bout[1]; }
    #pragma unroll
    for (int pass = 0; pass < 2; ++pass) {
        if ((wm >> 1) == pass) {
            int g = lane >> 2, t2 = (lane & 3)*2;
            #pragma unroll
            for (int mt = 0; mt < 2; ++mt) {
                #pragma unroll
                for (int nt = 0; nt < 8; ++nt) {
                    int r0 = (wm & 1)*32 + mt*16 + g;
                    int c0 = wn*64 + nt*8 + t2;
                    *(float2*)(stage + r0*STG_STRIDE + c0)     = make_float2(acc[mt][nt][0], acc[mt][nt][1]);
                    *(float2*)(stage + (r0+8)*STG_STRIDE + c0) = make_float2(acc[mt][nt][2], acc[mt][nt][3]);
                }
            }
        }
        __syncthreads();
        {
            int row = tid >> 2;              // 0..63
            int q4  = tid & 3;               // 32-col chunk
            long orow = blockRow + pass*64 + row;
            bool ok = orow < M;
            long rc = ok ? orow : (M-1);
            int beg = rowptr[rc];
            int end = rowptr[rc+1];          // rowptr[N_UD] == E_BIG
            float v[32];
            const float* sp = stage + row*STG_STRIDE + q4*32;
            #pragma unroll
            for (int j = 0; j < 8; ++j) {
                float4 t = *(const float4*)(sp + j*4);
                float4 b = *(const float4*)(sBias + q4*32 + j*4);
                v[4*j+0]=t.x+b.x; v[4*j+1]=t.y+b.y; v[4*j+2]=t.z+b.z; v[4*j+3]=t.w+b.w;
            }
            for (int e = beg; e < end; ++e) {
                const float4* tp = (const float4*)(tuser + (size_t)csrc[e]*H + q4*32);
                #pragma unroll
                for (int j = 0; j < 8; ++j) {
                    float4 u = tp[j];
                    v[4*j+0]+=u.x; v[4*j+1]+=u.y; v[4*j+2]+=u.z; v[4*j+3]+=u.w;
                }
            }
            if (ok) {
                float4* cp = (float4*)(C + orow*H + q4*32);
                #pragma unroll
                for (int j = 0; j < 8; ++j)
                    cp[j] = make_float4(v[4*j+0], v[4*j+1], v[4*j+2], v[4*j+3]);
            }
            if (MODE == 2) {
                float z0 = 0.f, z1 = 0.f;
                #pragma unroll
                for (int j = 0; j < 32; ++j) {
                    int col = q4*32 + j;
                    z0 += v[j] * sEx[2*col];
                    z1 += v[j] * sEx[2*col+1];
                }
                z0 += __shfl_xor_sync(0xffffffffu, z0, 1);
                z1 += __shfl_xor_sync(0xffffffffu, z1, 1);
                z0 += __shfl_xor_sync(0xffffffffu, z0, 2);
                z1 += __shfl_xor_sync(0xffffffffu, z1, 2);
                if (q4 == 0 && ok) {
                    z0 += bo0; z1 += bo1;
                    float m = fmaxf(z0, z1);
                    float l = m + logf(expf(z0 - m) + expf(z1 - m));
                    *(float2*)(pred + orow*2) = make_float2(z0 - l, z1 - l);
                }
            }
        }
        __syncthreads();
    }
}

// ---------------- launch ----------------
extern "C" void kernel_launch(void* const* d_in, const int* in_sizes, int n_in,
                              void* d_out, int out_size) {
    const float* x_ud   = (const float*)d_in[0];
    const float* W_feat = (const float*)d_in[1];
    const float* b_feat = (const float*)d_in[2];
    const float* emb_ud = (const float*)d_in[3];
    const float* emb_us = (const float*)d_in[4];
    const float* emb_sp = (const float*)d_in[5];
    const float* Wr1 = (const float*)d_in[6];
    const float* br1 = (const float*)d_in[7];
    const float* Wt1 = (const float*)d_in[8];
    const float* Wr2 = (const float*)d_in[9];
    const float* br2 = (const float*)d_in[10];
    const float* Wt2 = (const float*)d_in[11];
    const float* Wout = (const float*)d_in[12];
    const float* bout = (const float*)d_in[13];
    const int* nid_ud = (const int*)d_in[14];
    const int* nid_us = (const int*)d_in[15];
    const int* nid_sp = (const int*)d_in[16];
    const int* e0s = (const int*)d_in[17];
    const int* e0d = (const int*)d_in[18];
    const int* e1s = (const int*)d_in[19];
    const int* e1d = (const int*)d_in[20];
    const int* e2s = (const int*)d_in[21];
    const int* e2d = (const int*)d_in[22];
    const int* e3s = (const int*)d_in[23];
    const int* e3d = (const int*)d_in[24];

    float *p_hud0, *p_hud1, *p_user0, *p_user1, *p_sup0, *p_sup1, *p_tuser, *p_agg;
    int *p_rowptr, *p_csrc;
    __nv_bfloat16 *p_bhi, *p_blo;
    cudaGetSymbolAddress((void**)&p_hud0,  g_hud0);
    cudaGetSymbolAddress((void**)&p_hud1,  g_hud1);
    cudaGetSymbolAddress((void**)&p_user0, g_user0);
    cudaGetSymbolAddress((void**)&p_user1, g_user1);
    cudaGetSymbolAddress((void**)&p_sup0,  g_sup0);
    cudaGetSymbolAddress((void**)&p_sup1,  g_sup1);
    cudaGetSymbolAddress((void**)&p_tuser, g_tuser);
    cudaGetSymbolAddress((void**)&p_agg,   g_agg);
    cudaGetSymbolAddress((void**)&p_rowptr, g_rowptr);
    cudaGetSymbolAddress((void**)&p_csrc,   g_csrc);
    cudaGetSymbolAddress((void**)&p_bhi,    g_Bhi);
    cudaGetSymbolAddress((void**)&p_blo,    g_Blo);

    float* out    = (float*)d_out;
    float* o_pred = out;
    float* o_hud  = out + 1000000;
    float* o_user = out + 65000000;
    float* o_sup  = out + 65512000;

    cudaFuncSetAttribute(k_fused_mma<1>, cudaFuncAttributeMaxDynamicSharedMemorySize, TC_SMEM);
    cudaFuncSetAttribute(k_fused_mma<2>, cudaFuncAttributeMaxDynamicSharedMemorySize, TC_SMEM);

    const int T = 256;
    int gridZA    = (AGG_TOT/4 + T-1)/T;
    int gridZC    = (NA/4 + T-1)/T;
    int gridUs32  = (N_USER*32 + T-1)/T;
    int gridSp32  = (N_SUP*32 + T-1)/T;
    int gridES    = (E_SMALL*32 + T-1)/T;
    int gridE     = (E_BIG + T-1)/T;
    int gridPrep  = (2*HH + T-1)/T;

    // ---- init + combined CSR build + weight prep ----
    k_zero_agg<<<gridZA, T>>>();
    k_zero_cnt<<<gridZC, T>>>();
    k_hist2<<<gridE, T>>>(e1d, e0d);
    k_prepW<<<gridPrep, T>>>(Wt1 + 1*HH, Wt2 + 1*HH);
    k_gather_rows<<<gridUs32, T>>>(emb_us, nid_us, p_user0, N_USER);
    k_gather_rows<<<gridSp32, T>>>(emb_sp, nid_sp, p_sup0, N_SUP);
    k_bsum<<<NBLK, 256>>>();
    k_scan_top<<<1, 512>>>();
    k_scan_write<<<NBLK, 1024>>>();
    k_fill2<<<gridE, T>>>(e1s, e1d, e0s, e0d);

    // ---- layer 1 UD: tuser1, fused feat+GEMM+e1 CSR ----
    k_gemm_small<<<gridUs32, T>>>(p_user0, Wr1 + 1*HH, nullptr, p_tuser, N_USER, 0, 0);
    k_fused_mma<1><<<N_TILES, 256, TC_SMEM>>>(
        br1 + 1*H, p_tuser, p_rowptr, p_csrc, p_hud1,
        nullptr, x_ud, nid_ud, emb_ud, W_feat, b_feat, p_hud0,
        nullptr, nullptr, nullptr, p_bhi, p_blo, N_UD);

    // ---- layer 1 aggregations ----
    k_agg_user<false><<<N_USER, 128>>>(p_hud0, p_rowptr, p_csrc, p_agg + L1_UB);
    k_edge_add<false><<<gridES, T>>>(p_sup0,  e3s, e3d, p_agg + L1_US, E_SMALL);
    k_edge_add<false><<<gridES, T>>>(p_user0, e2s, e2d, p_agg + L1_S,  E_SMALL);

    // ---- layer 1 user/sup outputs (post-relu stored) ----
    k_gemm_small<<<gridUs32, T>>>(p_agg + L1_UB, Wr1 + 0*HH, br1 + 0*H, p_user1, N_USER, 0, 0);
    k_gemm_small<<<gridUs32, T>>>(p_agg + L1_US, Wr1 + 3*HH, br1 + 3*H, p_user1, N_USER, 1, 0);
    k_gemm_small<<<gridUs32, T>>>(p_user0,       Wt1 + 0*HH, nullptr,   p_user1, N_USER, 1, 0);
    k_gemm_small<<<gridUs32, T>>>(p_user0,       Wt1 + 3*HH, nullptr,   p_user1, N_USER, 1, 1);
    k_gemm_small<<<gridSp32, T>>>(p_agg + L1_S,  Wr1 + 2*HH, br1 + 2*H, p_sup1,  N_SUP,  0, 0);
    k_gemm_small<<<gridSp32, T>>>(p_sup0,        Wt1 + 2*HH, nullptr,   p_sup1,  N_SUP,  1, 1);

    // ---- layer 2: tuser2, fused relu+GEMM+e1 CSR+pred ----
    k_gemm_small<<<gridUs32, T>>>(p_user1, Wr2 + 1*HH, nullptr, p_tuser, N_USER, 0, 0);
    k_fused_mma<2><<<N_TILES, 256, TC_SMEM>>>(
        br2 + 1*H, p_tuser, p_rowptr, p_csrc, o_hud,
        p_hud1, nullptr, nullptr, nullptr, nullptr, nullptr, nullptr,
        Wout, bout, o_pred, p_bhi + HH, p_blo + HH, N_UD);

    // ---- layer 2 aggregations + user/sup outputs ----
    k_agg_user<true><<<N_USER, 128>>>(p_hud1, p_rowptr, p_csrc, p_agg + L2_UB);
    k_edge_add<false><<<gridES, T>>>(p_sup1,  e3s, e3d, p_agg + L2_US, E_SMALL);
    k_edge_add<false><<<gridES, T>>>(p_user1, e2s, e2d, p_agg + L2_S,  E_SMALL);
    k_gemm_small<<<gridUs32, T>>>(p_agg + L2_UB, Wr2 + 0*HH, br2 + 0*H, o_user, N_USER, 0, 0);
    k_gemm_small<<<gridUs32, T>>>(p_agg + L2_US, Wr2 + 3*HH, br2 + 3*H, o_user, N_USER, 1, 0);
    k_gemm_small<<<gridUs32, T>>>(p_user1,       Wt2 + 0*HH, nullptr,   o_user, N_USER, 1, 0);
    k_gemm_small<<<gridUs32, T>>>(p_user1,       Wt2 + 3*HH, nullptr,   o_user, N_USER, 1, 0);
    k_gemm_small<<<gridSp32, T>>>(p_agg + L2_S,  Wr2 + 2*HH, br2 + 2*H, o_sup,  N_SUP,  0, 0);
    k_gemm_small<<<gridSp32, T>>>(p_sup1,        Wt2 + 2*HH, nullptr,   o_sup,  N_SUP,  1, 0);

    (void)in_sizes; (void)n_in; (void)out_size;
}

// round 11
// speedup vs baseline: 1.0344x; 1.0344x over previous
#include <cuda_runtime.h>
#include <cuda_bf16.h>
#include <math.h>
#include <cstdint>

#define N_UD   500000
#define N_USER 4000
#define N_SUP  300
#define H      128
#define HH     (H*H)
#define E_BIG  500000
#define E_SMALL 4000
#define SZ_U   (N_USER*H)
#define SZ_S   (N_SUP*H)
#define NA     (N_UD + N_USER)   // combined CSR key space
#define N_TILES 3907             // ceil(N_UD/128)

// ---------------- scratch (static __device__ -> no allocations) ----------------
__device__ __align__(16) float g_hud1[(size_t)N_UD*H];
__device__ __align__(16) float g_user0[SZ_U];
__device__ __align__(16) float g_user1[SZ_U];
__device__ __align__(16) float g_sup0[SZ_S];
__device__ __align__(16) float g_sup1[SZ_S];
__device__ __align__(16) float g_tuser[SZ_U];

// bf16-split, transposed weights for the two big GEMMs: B[n][k] = W[k][n]
__device__ __align__(16) __nv_bfloat16 g_Bhi[2*HH];
__device__ __align__(16) __nv_bfloat16 g_Blo[2*HH];

// combined CSR: keys [0,N_UD) = e1 by dst (vals = e1 src user)
//               keys [N_UD,NA) = e0 by dst user (vals = e0 src UD)
__device__ int g_cnt[NA];       // zeroed statically + by k_cleanup each call
__device__ int g_rowptr[NA];
__device__ int g_pos[NA];
__device__ int g_csrc[2*E_BIG];

// single-pass scan scratch
#define SCAN_T    1024
#define SCAN_IT   4
#define SCAN_BLK  124            // ceil(NA / 4096)
__device__ int g_bsum[SCAN_BLK];
__device__ int g_arrive;         // zeroed statically + by k_cleanup

#define AGG_TOT (2*(2*SZ_U+SZ_S))
__device__ __align__(16) float g_agg[AGG_TOT];
#define L1_UB 0
#define L1_US (SZ_U)
#define L1_S  (2*SZ_U)
#define L2_UB (2*SZ_U+SZ_S)
#define L2_US (L2_UB+SZ_U)
#define L2_S  (L2_UB+2*SZ_U)

// ---------------- helpers ----------------
__device__ __forceinline__ uint32_t smem_to_u32(const void* p) {
    uint32_t a;
    asm("{ .reg .u64 t; cvta.to.shared.u64 t, %1; cvt.u32.u64 %0, t; }" : "=r"(a) : "l"(p));
    return a;
}
__device__ __forceinline__ void red_add_v4(float* p, float4 v) {
    asm volatile("red.global.add.v4.f32 [%0], {%1,%2,%3,%4};"
                 :: "l"(p), "f"(v.x), "f"(v.y), "f"(v.z), "f"(v.w) : "memory");
}
__device__ __forceinline__ void ldsm_x4(uint32_t* r, uint32_t addr) {
    asm volatile("ldmatrix.sync.aligned.m8n8.x4.shared.b16 {%0,%1,%2,%3}, [%4];"
        : "=r"(r[0]), "=r"(r[1]), "=r"(r[2]), "=r"(r[3]) : "r"(addr));
}
__device__ __forceinline__ void mma_bf16(float* d, const uint32_t* a, const uint32_t* b) {
    asm volatile("mma.sync.aligned.m16n8k16.row.col.f32.bf16.bf16.f32 "
        "{%0,%1,%2,%3}, {%4,%5,%6,%7}, {%8,%9}, {%0,%1,%2,%3};"
        : "+f"(d[0]), "+f"(d[1]), "+f"(d[2]), "+f"(d[3])
        : "r"(a[0]), "r"(a[1]), "r"(a[2]), "r"(a[3]), "r"(b[0]), "r"(b[1]));
}

// ================= L1 combo: zero agg | prepW | gathers | hist =================
#define CB_Z   2075     // zero agg: 531200 float4 / 256
#define CB_P   128      // prepW: 32768 / 256
#define CB_G1  500      // gather user: 4000*32/256
#define CB_G2  38       // gather sup: ceil(300*32/256)
#define CB_H   1954     // hist: ceil(500000/256)
#define CB_TOT (CB_Z + CB_P + CB_G1 + CB_G2 + CB_H)

__global__ __launch_bounds__(256)
void k_combo(const float* __restrict__ Wt1, const float* __restrict__ Wt2,
             const float* __restrict__ emb_us, const int* __restrict__ nid_us,
             const float* __restrict__ emb_sp, const int* __restrict__ nid_sp,
             const int* __restrict__ e1d, const int* __restrict__ e0d) {
    int b = blockIdx.x, t = threadIdx.x;
    if (b < CB_Z) {
        int g = b*256 + t;
        if (g < AGG_TOT/4) ((float4*)g_agg)[g] = make_float4(0.f,0.f,0.f,0.f);
    } else if (b < CB_Z + CB_P) {
        int i = (b - CB_Z)*256 + t;      // i < 2*HH
        int w = i >> 14;
        int r = i & (HH-1);
        int n = r >> 7, k = r & 127;
        const float* W = (w ? Wt2 : Wt1) + HH;   // Wt_1 (UD root)
        float v = W[k*H + n];
        __nv_bfloat16 hi = __float2bfloat16(v);
        g_Bhi[i] = hi;
        g_Blo[i] = __float2bfloat16(v - __bfloat162float(hi));
    } else if (b < CB_Z + CB_P + CB_G1) {
        int g = (b - CB_Z - CB_P)*256 + t;
        int row = g >> 5, lane = g & 31;
        int r = nid_us[row];
        float4 v = *(const float4*)(emb_us + (size_t)r*H + lane*4);
        *(float4*)(g_user0 + (size_t)row*H + lane*4) = v;
    } else if (b < CB_Z + CB_P + CB_G1 + CB_G2) {
        int g = (b - CB_Z - CB_P - CB_G1)*256 + t;
        int row = g >> 5, lane = g & 31;
        if (row < N_SUP) {
            int r = nid_sp[row];
            float4 v = *(const float4*)(emb_sp + (size_t)r*H + lane*4);
            *(float4*)(g_sup0 + (size_t)row*H + lane*4) = v;
        }
    } else {
        int e = (b - CB_Z - CB_P - CB_G1 - CB_G2)*256 + t;
        if (e < E_BIG) {
            atomicAdd(&g_cnt[e1d[e]], 1);
            atomicAdd(&g_cnt[N_UD + e0d[e]], 1);
        }
    }
}

// ================= L2: single-kernel exclusive scan over g_cnt[NA] =================
__global__ __launch_bounds__(SCAN_T)
void k_scan1() {
    __shared__ int s[SCAN_T];
    __shared__ int sboff;
    int b = blockIdx.x, t = threadIdx.x;
    int base = b*(SCAN_T*SCAN_IT) + t*SCAN_IT;
    int v[SCAN_IT];
    #pragma unroll
    for (int i = 0; i < SCAN_IT; ++i) {
        int idx = base + i;
        v[i] = (idx < NA) ? g_cnt[idx] : 0;
    }
    int ts = v[0] + v[1] + v[2] + v[3];
    s[t] = ts; __syncthreads();
    #pragma unroll
    for (int o = 1; o < SCAN_T; o <<= 1) {
        int x = (t >= o) ? s[t-o] : 0;
        __syncthreads(); s[t] += x; __syncthreads();
    }
    int texcl = s[t] - ts;
    int total = s[SCAN_T-1];
    if (t == 0) {
        g_bsum[b] = total;
        __threadfence();
        atomicAdd(&g_arrive, 1);
        while (atomicAdd(&g_arrive, 0) < gridDim.x) { }
        int sum = 0;
        for (int i = 0; i < b; ++i) sum += g_bsum[i];
        sboff = sum;
    }
    __syncthreads();
    int off = sboff + texcl;
    #pragma unroll
    for (int i = 0; i < SCAN_IT; ++i) {
        int idx = base + i;
        if (idx < NA) { g_rowptr[idx] = off; g_pos[idx] = off; }
        off += v[i];
    }
}

// ================= L3: CSR fill + tuser GEMM combined =================
#define FT_F   1954     // fill: ceil(500000/256)
#define FT_G   500      // tuser gemm: 4000*32/256
__global__ __launch_bounds__(256)
void k_fill_tuser(const int* __restrict__ e1s, const int* __restrict__ e1d,
                  const int* __restrict__ e0s, const int* __restrict__ e0d,
                  const float* __restrict__ A, const float* __restrict__ W) {
    int b = blockIdx.x, t = threadIdx.x;
    if (b < FT_F) {
        int e = b*256 + t;
        if (e < E_BIG) {
            int p = atomicAdd(&g_pos[e1d[e]], 1);
            g_csrc[p] = e1s[e];
            int q = atomicAdd(&g_pos[N_UD + e0d[e]], 1);
            g_csrc[q] = e0s[e];
        }
    } else {
        int g = (b - FT_F)*256 + t;
        int row = g >> 5, lane = g & 31;
        const float* a = A + (size_t)row*H;
        float4 acc = make_float4(0.f,0.f,0.f,0.f);
        #pragma unroll 8
        for (int k = 0; k < H; ++k) {
            float av = __ldg(a + k);
            float4 w = *(const float4*)(W + (size_t)k*H + lane*4);
            acc.x += av*w.x; acc.y += av*w.y; acc.z += av*w.z; acc.w += av*w.w;
        }
        *(float4*)(g_tuser + (size_t)row*H + lane*4) = acc;
    }
}

// ---------------- cleanup: restore zeroed state for next call ----------------
__global__ void k_cleanup() {
    int g = blockIdx.x * blockDim.x + threadIdx.x;
    if (g < NA/4) ((int4*)g_cnt)[g] = make_int4(0,0,0,0);
    if (g == 0) g_arrive = 0;
}

// ---------------- edge scatter-add (small edge sets only) ----------------
__global__ void k_edge_add(const float* __restrict__ src_tab, const int* __restrict__ es,
                           const int* __restrict__ ed, float* __restrict__ dst_tab, int E) {
    int g = blockIdx.x * blockDim.x + threadIdx.x;
    int e = g >> 5;
    if (e >= E) return;
    int lane = g & 31;
    int s = es[e], d = ed[e];
    float4 v = *(const float4*)(src_tab + (size_t)s*H + lane*4);
    red_add_v4(dst_tab + (size_t)d*H + lane*4, v);
}

// ---------------- e0 L1 aggregation: recompute feat per edge (no hud0) ----------------
// agg[u] = sum over e0 edges dst==u of (x_ud[s]@Wf + bf + emb_ud[nid[s]])
__global__ __launch_bounds__(128)
void k_agg_feat(const float* __restrict__ xud, const int* __restrict__ nid,
                const float* __restrict__ emb, const float* __restrict__ Wf,
                const float* __restrict__ bf,
                const int* __restrict__ rowptr, const int* __restrict__ csrc,
                float* __restrict__ aggUB) {
    __shared__ float sW[5*H];
    __shared__ float sb[H];
    int u = blockIdx.x;
    int t = threadIdx.x;
    for (int i = t; i < 5*H; i += 128) sW[i] = Wf[i];
    sb[t] = bf[t];
    __syncthreads();
    int beg = rowptr[N_UD + u];
    int end = (u == N_USER-1) ? 2*E_BIG : rowptr[N_UD + u + 1];
    float w0 = sW[0*H+t], w1 = sW[1*H+t], w2 = sW[2*H+t], w3 = sW[3*H+t], w4 = sW[4*H+t];
    float bb = sb[t];
    float acc = 0.f;
    #pragma unroll 2
    for (int e = beg; e < end; ++e) {
        int s = csrc[e];
        int nr = __ldg(nid + s);
        const float* xp = xud + (size_t)s*5;
        float x0 = __ldg(xp), x1 = __ldg(xp+1), x2 = __ldg(xp+2),
              x3 = __ldg(xp+3), x4 = __ldg(xp+4);
        float v = bb + emb[(size_t)nr*H + t]
                + x0*w0 + x1*w1 + x2*w2 + x3*w3 + x4*w4;
        acc += v;
    }
    aggUB[(size_t)u*H + t] = acc;
}

// ---------------- e0 L2 aggregation by gather (relu(hud1)) ----------------
__global__ __launch_bounds__(128)
void k_agg_user(const float* __restrict__ hud, const int* __restrict__ rowptr,
                const int* __restrict__ csrc, float* __restrict__ aggUB) {
    int u = blockIdx.x;
    int tid = threadIdx.x;
    int beg = rowptr[N_UD + u];
    int end = (u == N_USER-1) ? 2*E_BIG : rowptr[N_UD + u + 1];
    float acc = 0.f;
    int e = beg;
    for (; e + 4 <= end; e += 4) {
        int s0 = csrc[e], s1 = csrc[e+1], s2 = csrc[e+2], s3 = csrc[e+3];
        float v0 = fmaxf(hud[(size_t)s0*H + tid], 0.f);
        float v1 = fmaxf(hud[(size_t)s1*H + tid], 0.f);
        float v2 = fmaxf(hud[(size_t)s2*H + tid], 0.f);
        float v3 = fmaxf(hud[(size_t)s3*H + tid], 0.f);
        acc += (v0 + v1) + (v2 + v3);
    }
    for (; e < end; ++e) acc += fmaxf(hud[(size_t)csrc[e]*H + tid], 0.f);
    aggUB[(size_t)u*H + tid] = acc;
}

// ---------------- small GEMM ----------------
__global__ void k_gemm_small(const float* __restrict__ A, const float* __restrict__ W,
                             const float* __restrict__ bias, float* __restrict__ C,
                             int M, int accum, int relu) {
    int g = blockIdx.x * blockDim.x + threadIdx.x;
    int row = g >> 5;
    if (row >= M) return;
    int lane = g & 31;
    const float* a = A + (size_t)row*H;
    float4 acc = make_float4(0.f,0.f,0.f,0.f);
    #pragma unroll 8
    for (int k = 0; k < H; ++k) {
        float av = __ldg(a + k);
        float4 w = *(const float4*)(W + (size_t)k*H + lane*4);
        acc.x += av*w.x; acc.y += av*w.y; acc.z += av*w.z; acc.w += av*w.w;
    }
    if (bias) {
        float4 b = *(const float4*)(bias + lane*4);
        acc.x += b.x; acc.y += b.y; acc.z += b.z; acc.w += b.w;
    }
    float* cp = C + (size_t)row*H + lane*4;
    if (accum) {
        float4 old = *(float4*)cp;
        acc.x += old.x; acc.y += old.y; acc.z += old.z; acc.w += old.w;
    }
    if (relu) { acc.x=fmaxf(acc.x,0.f); acc.y=fmaxf(acc.y,0.f); acc.z=fmaxf(acc.z,0.f); acc.w=fmaxf(acc.w,0.f); }
    *(float4*)cp = acc;
}

// ================= fused big GEMM via mma.sync bf16 3-split (R5/R9 config) =================
// MODE 1: A = feat(x_ud,Wf,bf,emb[nid]); C = A@W + b + e1-CSR(tuser)
// MODE 2: A = relu(Ain); C = A@W + b + e1-CSR(tuser); pred = log_softmax(C@Wout + bout)
#define PADB     272
#define SM_W     0
#define SM_WLO   34816
#define SM_A     69632
#define SM_ALO   104448
#define SM_STAGE 69632
#define SM_BIAS  139264
#define SM_EX    139776
#define TC_SMEM  143360
#define STG_STRIDE 132

template<int MODE>
__global__ __launch_bounds__(256, 1)
void k_fused_mma(const float* __restrict__ bias,
                 const float* __restrict__ tuser, const int* __restrict__ rowptr,
                 const int* __restrict__ csrc, float* __restrict__ C,
                 const float* __restrict__ Ain,
                 const float* __restrict__ xud, const int* __restrict__ nid,
                 const float* __restrict__ emb, const float* __restrict__ Wf,
                 const float* __restrict__ bf,
                 const float* __restrict__ Wout, const float* __restrict__ bout,
                 float* __restrict__ pred, const __nv_bfloat16* __restrict__ Bh,
                 const __nv_bfloat16* __restrict__ Bl, int M) {
    extern __shared__ char smem[];
    uint32_t smem_base = smem_to_u32(smem);
    float* sBias = (float*)(smem + SM_BIAS);
    float* sEx   = (float*)(smem + SM_EX);

    int tid  = threadIdx.x;
    int wid  = tid >> 5;
    int lane = tid & 31;
    long blockRow = (long)blockIdx.x * 128;

    if (tid < 128) sBias[tid] = bias[tid];
    if (MODE == 1) {
        for (int i = tid; i < 768; i += 256) sEx[i] = (i < 640) ? Wf[i] : bf[i-640];
    } else {
        if (tid < 256) sEx[tid] = Wout[tid];
    }
    for (int i = tid; i < 2048; i += 256) {
        uint4 vh = ((const uint4*)Bh)[i];
        uint4 vl = ((const uint4*)Bl)[i];
        int n  = i >> 4;
        int kq = i & 15;
        int dst = n*PADB + kq*16;
        *(uint4*)(smem + SM_W   + dst) = vh;
        *(uint4*)(smem + SM_WLO + dst) = vl;
    }
    __syncthreads();

    // ---- prologue: build 128x128 A tile, bf16 hi/lo -> smem ----
    {
        int prow  = tid & 127;
        int khalf = tid >> 7;
        long rowReal = blockRow + prow;
        bool rok = rowReal < M;
        long rsrc = rok ? rowReal : (M-1);
        float x0=0,x1=0,x2=0,x3=0,x4=0; long nr = 0;
        if (MODE == 1) {
            nr = nid[rsrc];
            const float* xp = xud + rsrc*5;
            x0=xp[0]; x1=xp[1]; x2=xp[2]; x3=xp[3]; x4=xp[4];
        }
        #pragma unroll
        for (int j = 0; j < 16; ++j) {
            int k = khalf*64 + j*4;
            float4 o;
            if (MODE == 1) {
                float4 e  = *(const float4*)(emb + nr*H + k);
                float4 w0 = *(const float4*)(sEx + 0*H + k);
                float4 w1 = *(const float4*)(sEx + 1*H + k);
                float4 w2 = *(const float4*)(sEx + 2*H + k);
                float4 w3 = *(const float4*)(sEx + 3*H + k);
                float4 w4 = *(const float4*)(sEx + 4*H + k);
                float4 bb = *(const float4*)(sEx + 5*H + k);
                o.x = bb.x + e.x + x0*w0.x + x1*w1.x + x2*w2.x + x3*w3.x + x4*w4.x;
                o.y = bb.y + e.y + x0*w0.y + x1*w1.y + x2*w2.y + x3*w3.y + x4*w4.y;
                o.z = bb.z + e.z + x0*w0.z + x1*w1.z + x2*w2.z + x3*w3.z + x4*w4.z;
                o.w = bb.w + e.w + x0*w0.w + x1*w1.w + x2*w2.w + x3*w3.w + x4*w4.w;
            } else {
                o = *(const float4*)(Ain + rsrc*H + k);
                o.x=fmaxf(o.x,0.f); o.y=fmaxf(o.y,0.f); o.z=fmaxf(o.z,0.f); o.w=fmaxf(o.w,0.f);
            }
            uint32_t h0, h1;
            asm("cvt.rn.bf16x2.f32 %0, %1, %2;" : "=r"(h0) : "f"(o.y), "f"(o.x));
            asm("cvt.rn.bf16x2.f32 %0, %1, %2;" : "=r"(h1) : "f"(o.w), "f"(o.z));
            float hx = __uint_as_float(h0 << 16);
            float hy = __uint_as_float(h0 & 0xffff0000u);
            float hz = __uint_as_float(h1 << 16);
            float hw = __uint_as_float(h1 & 0xffff0000u);
            uint32_t l0, l1;
            asm("cvt.rn.bf16x2.f32 %0, %1, %2;" : "=r"(l0) : "f"(o.y - hy), "f"(o.x - hx));
            asm("cvt.rn.bf16x2.f32 %0, %1, %2;" : "=r"(l1) : "f"(o.w - hw), "f"(o.z - hz));
            uint2 hh; hh.x = h0; hh.y = h1;
            uint2 ll; ll.x = l0; ll.y = l1;
            int off = prow*PADB + k*2;
            *(uint2*)(smem + SM_A   + off) = hh;
            *(uint2*)(smem + SM_ALO + off) = ll;
        }
    }
    __syncthreads();

    // ---- MMA mainloop: warp (wm, wn) owns 32 rows x 64 cols ----
    int wm = wid & 3, wn = wid >> 2;
    float acc[2][8][4];
    #pragma unroll
    for (int mt = 0; mt < 2; ++mt)
        #pragma unroll
        for (int nt = 0; nt < 8; ++nt)
            #pragma unroll
            for (int q = 0; q < 4; ++q) acc[mt][nt][q] = 0.f;

    #pragma unroll
    for (int kc = 0; kc < 8; ++kc) {
        uint32_t ah[2][4], al[2][4];
        #pragma unroll
        for (int mt = 0; mt < 2; ++mt) {
            int row  = wm*32 + mt*16 + (lane & 15);
            int koff = kc*16 + (lane >> 4)*8;
            uint32_t off = row*PADB + koff*2;
            ldsm_x4(ah[mt], smem_base + SM_A   + off);
            ldsm_x4(al[mt], smem_base + SM_ALO + off);
        }
        uint32_t bh[16], bl[16];
        #pragma unroll
        for (int g = 0; g < 4; ++g) {
            int n    = wn*64 + g*16 + (lane & 7) + (lane >> 4)*8;
            int koff = kc*16 + ((lane >> 3) & 1)*8;
            uint32_t off = n*PADB + koff*2;
            ldsm_x4(bh + g*4, smem_base + SM_W   + off);
            ldsm_x4(bl + g*4, smem_base + SM_WLO + off);
        }
        #pragma unroll
        for (int mt = 0; mt < 2; ++mt) {
            #pragma unroll
            for (int nt = 0; nt < 8; ++nt) {
                const uint32_t* bph = bh + (nt >> 1)*4 + (nt & 1)*2;
                const uint32_t* bpl = bl + (nt >> 1)*4 + (nt & 1)*2;
                mma_bf16(acc[mt][nt], ah[mt], bph);
                mma_bf16(acc[mt][nt], ah[mt], bpl);
                mma_bf16(acc[mt][nt], al[mt], bph);
            }
        }
    }

    // ---- stage accumulators to smem (overlays A) ----
    __syncthreads();
    float* stage = (float*)(smem + SM_STAGE);
    {
        int g = lane >> 2, t2 = (lane & 3)*2;
        #pragma unroll
        for (int mt = 0; mt < 2; ++mt) {
            #pragma unroll
            for (int nt = 0; nt < 8; ++nt) {
                int r0 = wm*32 + mt*16 + g;
                int c0 = wn*64 + nt*8 + t2;
                *(float2*)(stage + r0*STG_STRIDE + c0)     = make_float2(acc[mt][nt][0], acc[mt][nt][1]);
                *(float2*)(stage + (r0+8)*STG_STRIDE + c0) = make_float2(acc[mt][nt][2], acc[mt][nt][3]);
            }
        }
    }
    __syncthreads();

    // ---- epilogue: bias + e1-CSR + store (+pred) ----
    {
        int row  = tid >> 1;
        int half = tid & 1;
        long orow = blockRow + row;
        bool ok = orow < M;
        long rc = ok ? orow : (M-1);
        int beg = rowptr[rc];
        int end = rowptr[rc+1];   // rowptr[N_UD] == E_BIG (start of e0 section)
        float v[64];
        const float* sp = stage + row*STG_STRIDE + half*64;
        #pragma unroll
        for (int j = 0; j < 16; ++j) {
            float4 t = *(const float4*)(sp + j*4);
            float4 b = *(const float4*)(sBias + half*64 + j*4);
            v[4*j+0]=t.x+b.x; v[4*j+1]=t.y+b.y; v[4*j+2]=t.z+b.z; v[4*j+3]=t.w+b.w;
        }
        for (int e = beg; e < end; ++e) {
            const float4* tp = (const float4*)(tuser + (size_t)csrc[e]*H + half*64);
            #pragma unroll
            for (int q = 0; q < 16; ++q) {
                float4 u = tp[q];
                v[4*q+0]+=u.x; v[4*q+1]+=u.y; v[4*q+2]+=u.z; v[4*q+3]+=u.w;
            }
        }
        if (ok) {
            float4* cp = (float4*)(C + orow*H + half*64);
            #pragma unroll
            for (int j = 0; j < 16; ++j)
                cp[j] = make_float4(v[4*j+0], v[4*j+1], v[4*j+2], v[4*j+3]);
        }
        if (MODE == 2) {
            float z0 = 0.f, z1 = 0.f;
            #pragma unroll
            for (int j = 0; j < 64; ++j) {
                int col = half*64 + j;
                z0 += v[j] * sEx[2*col];
                z1 += v[j] * sEx[2*col+1];
            }
            z0 += __shfl_xor_sync(0xffffffffu, z0, 1);
            z1 += __shfl_xor_sync(0xffffffffu, z1, 1);
            if (half == 0 && ok) {
                z0 += bout[0]; z1 += bout[1];
                float m = fmaxf(z0, z1);
                float l = m + logf(expf(z0 - m) + expf(z1 - m));
                *(float2*)(pred + orow*2) = make_float2(z0 - l, z1 - l);
            }
        }
    }
}

// ---------------- launch ----------------
extern "C" void kernel_launch(void* const* d_in, const int* in_sizes, int n_in,
                              void* d_out, int out_size) {
    const float* x_ud   = (const float*)d_in[0];
    const float* W_feat = (const float*)d_in[1];
    const float* b_feat = (const float*)d_in[2];
    const float* emb_ud = (const float*)d_in[3];
    const float* emb_us = (const float*)d_in[4];
    const float* emb_sp = (const float*)d_in[5];
    const float* Wr1 = (const float*)d_in[6];
    const float* br1 = (const float*)d_in[7];
    const float* Wt1 = (const float*)d_in[8];
    const float* Wr2 = (const float*)d_in[9];
    const float* br2 = (const float*)d_in[10];
    const float* Wt2 = (const float*)d_in[11];
    const float* Wout = (const float*)d_in[12];
    const float* bout = (const float*)d_in[13];
    const int* nid_ud = (const int*)d_in[14];
    const int* nid_us = (const int*)d_in[15];
    const int* nid_sp = (const int*)d_in[16];
    const int* e0s = (const int*)d_in[17];
    const int* e0d = (const int*)d_in[18];
    const int* e1s = (const int*)d_in[19];
    const int* e1d = (const int*)d_in[20];
    const int* e2s = (const int*)d_in[21];
    const int* e2d = (const int*)d_in[22];
    const int* e3s = (const int*)d_in[23];
    const int* e3d = (const int*)d_in[24];

    float *p_hud1, *p_user0, *p_user1, *p_sup0, *p_sup1, *p_tuser, *p_agg;
    int *p_rowptr, *p_csrc;
    __nv_bfloat16 *p_bhi, *p_blo;
    cudaGetSymbolAddress((void**)&p_hud1,  g_hud1);
    cudaGetSymbolAddress((void**)&p_user0, g_user0);
    cudaGetSymbolAddress((void**)&p_user1, g_user1);
    cudaGetSymbolAddress((void**)&p_sup0,  g_sup0);
    cudaGetSymbolAddress((void**)&p_sup1,  g_sup1);
    cudaGetSymbolAddress((void**)&p_tuser, g_tuser);
    cudaGetSymbolAddress((void**)&p_agg,   g_agg);
    cudaGetSymbolAddress((void**)&p_rowptr, g_rowptr);
    cudaGetSymbolAddress((void**)&p_csrc,   g_csrc);
    cudaGetSymbolAddress((void**)&p_bhi,    g_Bhi);
    cudaGetSymbolAddress((void**)&p_blo,    g_Blo);

    float* out    = (float*)d_out;
    float* o_pred = out;
    float* o_hud  = out + 1000000;
    float* o_user = out + 65000000;
    float* o_sup  = out + 65512000;

    cudaFuncSetAttribute(k_fused_mma<1>, cudaFuncAttributeMaxDynamicSharedMemorySize, TC_SMEM);
    cudaFuncSetAttribute(k_fused_mma<2>, cudaFuncAttributeMaxDynamicSharedMemorySize, TC_SMEM);

    const int T = 256;
    int gridUs32  = (N_USER*32 + T-1)/T;
    int gridSp32  = (N_SUP*32 + T-1)/T;
    int gridES    = (E_SMALL*32 + T-1)/T;
    int gridClean = (NA/4 + T-1)/T;

    // ---- L1..L3: fully merged init (3 launches) ----
    k_combo<<<CB_TOT, T>>>(Wt1, Wt2, emb_us, nid_us, emb_sp, nid_sp, e1d, e0d);
    k_scan1<<<SCAN_BLK, SCAN_T>>>();
    k_fill_tuser<<<FT_F + FT_G, T>>>(e1s, e1d, e0s, e0d, p_user0, Wr1 + 1*HH);

    // ---- L4 (ncu-profiled): fused feat+GEMM+e1 CSR ----
    k_fused_mma<1><<<N_TILES, 256, TC_SMEM>>>(
        br1 + 1*H, p_tuser, p_rowptr, p_csrc, p_hud1,
        nullptr, x_ud, nid_ud, emb_ud, W_feat, b_feat,
        nullptr, nullptr, nullptr, p_bhi, p_blo, N_UD);

    // ---- layer 1 aggregations ----
    k_agg_feat<<<N_USER, 128>>>(x_ud, nid_ud, emb_ud, W_feat, b_feat,
                                p_rowptr, p_csrc, p_agg + L1_UB);
    k_edge_add<<<gridES, T>>>(p_sup0,  e3s, e3d, p_agg + L1_US, E_SMALL);
    k_edge_add<<<gridES, T>>>(p_user0, e2s, e2d, p_agg + L1_S,  E_SMALL);

    // ---- layer 1 user/sup outputs (post-relu stored) ----
    k_gemm_small<<<gridUs32, T>>>(p_agg + L1_UB, Wr1 + 0*HH, br1 + 0*H, p_user1, N_USER, 0, 0);
    k_gemm_small<<<gridUs32, T>>>(p_agg + L1_US, Wr1 + 3*HH, br1 + 3*H, p_user1, N_USER, 1, 0);
    k_gemm_small<<<gridUs32, T>>>(p_user0,       Wt1 + 0*HH, nullptr,   p_user1, N_USER, 1, 0);
    k_gemm_small<<<gridUs32, T>>>(p_user0,       Wt1 + 3*HH, nullptr,   p_user1, N_USER, 1, 1);
    k_gemm_small<<<gridSp32, T>>>(p_agg + L1_S,  Wr1 + 2*HH, br1 + 2*H, p_sup1,  N_SUP,  0, 0);
    k_gemm_small<<<gridSp32, T>>>(p_sup0,        Wt1 + 2*HH, nullptr,   p_sup1,  N_SUP,  1, 1);

    // ---- layer 2: tuser2, fused relu+GEMM+e1 CSR+pred ----
    k_gemm_small<<<gridUs32, T>>>(p_user1, Wr2 + 1*HH, nullptr, p_tuser, N_USER, 0, 0);
    k_fused_mma<2><<<N_TILES, 256, TC_SMEM>>>(
        br2 + 1*H, p_tuser, p_rowptr, p_csrc, o_hud,
        p_hud1, nullptr, nullptr, nullptr, nullptr, nullptr,
        Wout, bout, o_pred, p_bhi + HH, p_blo + HH, N_UD);

    // ---- layer 2 aggregations + user/sup outputs ----
    k_agg_user<<<N_USER, 128>>>(p_hud1, p_rowptr, p_csrc, p_agg + L2_UB);
    k_edge_add<<<gridES, T>>>(p_sup1,  e3s, e3d, p_agg + L2_US, E_SMALL);
    k_edge_add<<<gridES, T>>>(p_user1, e2s, e2d, p_agg + L2_S,  E_SMALL);
    k_gemm_small<<<gridUs32, T>>>(p_agg + L2_UB, Wr2 + 0*HH, br2 + 0*H, o_user, N_USER, 0, 0);
    k_gemm_small<<<gridUs32, T>>>(p_agg + L2_US, Wr2 + 3*HH, br2 + 3*H, o_user, N_USER, 1, 0);
    k_gemm_small<<<gridUs32, T>>>(p_user1,       Wt2 + 0*HH, nullptr,   o_user, N_USER, 1, 0);
    k_gemm_small<<<gridUs32, T>>>(p_user1,       Wt2 + 3*HH, nullptr,   o_user, N_USER, 1, 0);
    k_gemm_small<<<gridSp32, T>>>(p_agg + L2_S,  Wr2 + 2*HH, br2 + 2*H, o_sup,  N_SUP,  0, 0);
    k_gemm_small<<<gridSp32, T>>>(p_sup1,        Wt2 + 2*HH, nullptr,   o_sup,  N_SUP,  1, 0);

    // ---- cleanup: restore zeroed counters/flags for next deterministic call ----
    k_cleanup<<<gridClean, T>>>();

    (void)in_sizes; (void)n_in; (void)out_size;
}

// round 12
// speedup vs baseline: 1.1531x; 1.1148x over previous
#include <cuda_runtime.h>
#include <cuda_bf16.h>
#include <math.h>
#include <cstdint>

#define N_UD   500000
#define N_USER 4000
#define N_SUP  300
#define H      128
#define HH     (H*H)
#define E_BIG  500000
#define E_SMALL 4000
#define SZ_U   (N_USER*H)
#define SZ_S   (N_SUP*H)
#define NA     (N_UD + N_USER)   // combined CSR key space
#define N_TILES 3907             // ceil(N_UD/128)

// ---------------- scratch (static __device__ -> no allocations) ----------------
__device__ __align__(16) float g_hud1[(size_t)N_UD*H];
__device__ __align__(16) float g_user0[SZ_U];
__device__ __align__(16) float g_user1[SZ_U];
__device__ __align__(16) float g_sup0[SZ_S];
__device__ __align__(16) float g_sup1[SZ_S];
__device__ __align__(16) float g_tuser[SZ_U];

// fragment-ordered bf16-split weights for the two big GEMMs (mma B operand layout)
// index: ((layer*64 + g16*8 + kc)*32 + lane) -> uint4 {m0,m1,m2,m3}
__device__ __align__(16) uint4 g_Bfh[2*2048];
__device__ __align__(16) uint4 g_Bfl[2*2048];

// combined CSR: keys [0,N_UD) = e1 by dst (vals = e1 src user)
//               keys [N_UD,NA) = e0 by dst user (vals = e0 src UD)
__device__ int g_cnt[NA];       // zeroed statically + by k_cleanup each call
__device__ int g_rowptr[NA];
__device__ int g_pos[NA];
__device__ int g_csrc[2*E_BIG];

// single-pass scan scratch
#define SCAN_T    1024
#define SCAN_IT   4
#define SCAN_BLK  124            // ceil(NA / 4096)
__device__ int g_bsum[SCAN_BLK];
__device__ int g_arrive;         // zeroed statically + by k_cleanup

#define AGG_TOT (2*(2*SZ_U+SZ_S))
__device__ __align__(16) float g_agg[AGG_TOT];
#define L1_UB 0
#define L1_US (SZ_U)
#define L1_S  (2*SZ_U)
#define L2_UB (2*SZ_U+SZ_S)
#define L2_US (L2_UB+SZ_U)
#define L2_S  (L2_UB+2*SZ_U)

// ---------------- helpers ----------------
__device__ __forceinline__ uint32_t smem_to_u32(const void* p) {
    uint32_t a;
    asm("{ .reg .u64 t; cvta.to.shared.u64 t, %1; cvt.u32.u64 %0, t; }" : "=r"(a) : "l"(p));
    return a;
}
__device__ __forceinline__ void red_add_v4(float* p, float4 v) {
    asm volatile("red.global.add.v4.f32 [%0], {%1,%2,%3,%4};"
                 :: "l"(p), "f"(v.x), "f"(v.y), "f"(v.z), "f"(v.w) : "memory");
}
__device__ __forceinline__ void ldsm_x4(uint32_t* r, uint32_t addr) {
    asm volatile("ldmatrix.sync.aligned.m8n8.x4.shared.b16 {%0,%1,%2,%3}, [%4];"
        : "=r"(r[0]), "=r"(r[1]), "=r"(r[2]), "=r"(r[3]) : "r"(addr));
}
__device__ __forceinline__ void mma_bf16(float* d, const uint32_t* a, uint32_t b0, uint32_t b1) {
    asm volatile("mma.sync.aligned.m16n8k16.row.col.f32.bf16.bf16.f32 "
        "{%0,%1,%2,%3}, {%4,%5,%6,%7}, {%8,%9}, {%0,%1,%2,%3};"
        : "+f"(d[0]), "+f"(d[1]), "+f"(d[2]), "+f"(d[3])
        : "r"(a[0]), "r"(a[1]), "r"(a[2]), "r"(a[3]), "r"(b0), "r"(b1));
}

// ================= L1 combo: zero agg | prepW(frag) | gathers | hist =================
#define CB_Z   2075     // zero agg: 531200 float4 / 256
#define CB_P   128      // prepW: 32768 / 256
#define CB_G1  500      // gather user
#define CB_G2  38       // gather sup
#define CB_H   1954     // hist
#define CB_TOT (CB_Z + CB_P + CB_G1 + CB_G2 + CB_H)

__global__ __launch_bounds__(256)
void k_combo(const float* __restrict__ Wt1, const float* __restrict__ Wt2,
             const float* __restrict__ emb_us, const int* __restrict__ nid_us,
             const float* __restrict__ emb_sp, const int* __restrict__ nid_sp,
             const int* __restrict__ e1d, const int* __restrict__ e0d) {
    int b = blockIdx.x, t = threadIdx.x;
    if (b < CB_Z) {
        int g = b*256 + t;
        if (g < AGG_TOT/4) ((float4*)g_agg)[g] = make_float4(0.f,0.f,0.f,0.f);
    } else if (b < CB_Z + CB_P) {
        int i = (b - CB_Z)*256 + t;      // i < 2*HH
        int w = i >> 14;
        int r = i & (HH-1);
        int n = r >> 7, k = r & 127;
        const float* W = (w ? Wt2 : Wt1) + HH;   // Wt_1 (UD root)
        float v = W[k*H + n];                     // B[n][k] = W[k][n]
        __nv_bfloat16 hi = __float2bfloat16(v);
        __nv_bfloat16 lo = __float2bfloat16(v - __bfloat162float(hi));
        // mma B fragment layout
        int g16 = n >> 4, kc = k >> 4;
        int m = (((n >> 3) & 1) << 1) | ((k >> 3) & 1);
        int lane = ((n & 7) << 2) | ((k & 7) >> 1);
        int base = (((w*64 + g16*8 + kc)*32 + lane) << 2) | m;   // uint32 index
        ((__nv_bfloat16*)g_Bfh)[base*2 + (k & 1)] = hi;
        ((__nv_bfloat16*)g_Bfl)[base*2 + (k & 1)] = lo;
    } else if (b < CB_Z + CB_P + CB_G1) {
        int g = (b - CB_Z - CB_P)*256 + t;
        int row = g >> 5, lane = g & 31;
        int r = nid_us[row];
        float4 v = *(const float4*)(emb_us + (size_t)r*H + lane*4);
        *(float4*)(g_user0 + (size_t)row*H + lane*4) = v;
    } else if (b < CB_Z + CB_P + CB_G1 + CB_G2) {
        int g = (b - CB_Z - CB_P - CB_G1)*256 + t;
        int row = g >> 5, lane = g & 31;
        if (row < N_SUP) {
            int r = nid_sp[row];
            float4 v = *(const float4*)(emb_sp + (size_t)r*H + lane*4);
            *(float4*)(g_sup0 + (size_t)row*H + lane*4) = v;
        }
    } else {
        int e = (b - CB_Z - CB_P - CB_G1 - CB_G2)*256 + t;
        if (e < E_BIG) {
            atomicAdd(&g_cnt[e1d[e]], 1);
            atomicAdd(&g_cnt[N_UD + e0d[e]], 1);
        }
    }
}

// ================= L2: single-kernel exclusive scan over g_cnt[NA] =================
__global__ __launch_bounds__(SCAN_T)
void k_scan1() {
    __shared__ int s[SCAN_T];
    __shared__ int sboff;
    int b = blockIdx.x, t = threadIdx.x;
    int base = b*(SCAN_T*SCAN_IT) + t*SCAN_IT;
    int v[SCAN_IT];
    #pragma unroll
    for (int i = 0; i < SCAN_IT; ++i) {
        int idx = base + i;
        v[i] = (idx < NA) ? g_cnt[idx] : 0;
    }
    int ts = v[0] + v[1] + v[2] + v[3];
    s[t] = ts; __syncthreads();
    #pragma unroll
    for (int o = 1; o < SCAN_T; o <<= 1) {
        int x = (t >= o) ? s[t-o] : 0;
        __syncthreads(); s[t] += x; __syncthreads();
    }
    int texcl = s[t] - ts;
    if (t == 0) {
        g_bsum[b] = s[SCAN_T-1];
        __threadfence();
        atomicAdd(&g_arrive, 1);
        while (atomicAdd(&g_arrive, 0) < gridDim.x) { }
        int sum = 0;
        for (int i = 0; i < b; ++i) sum += g_bsum[i];
        sboff = sum;
    }
    __syncthreads();
    int off = sboff + texcl;
    #pragma unroll
    for (int i = 0; i < SCAN_IT; ++i) {
        int idx = base + i;
        if (idx < NA) { g_rowptr[idx] = off; g_pos[idx] = off; }
        off += v[i];
    }
}

// ================= L3: CSR fill + tuser GEMM combined =================
#define FT_F   1954
#define FT_G   500
__global__ __launch_bounds__(256)
void k_fill_tuser(const int* __restrict__ e1s, const int* __restrict__ e1d,
                  const int* __restrict__ e0s, const int* __restrict__ e0d,
                  const float* __restrict__ A, const float* __restrict__ W) {
    int b = blockIdx.x, t = threadIdx.x;
    if (b < FT_F) {
        int e = b*256 + t;
        if (e < E_BIG) {
            int p = atomicAdd(&g_pos[e1d[e]], 1);
            g_csrc[p] = e1s[e];
            int q = atomicAdd(&g_pos[N_UD + e0d[e]], 1);
            g_csrc[q] = e0s[e];
        }
    } else {
        int g = (b - FT_F)*256 + t;
        int row = g >> 5, lane = g & 31;
        const float* a = A + (size_t)row*H;
        float4 acc = make_float4(0.f,0.f,0.f,0.f);
        #pragma unroll 8
        for (int k = 0; k < H; ++k) {
            float av = __ldg(a + k);
            float4 w = *(const float4*)(W + (size_t)k*H + lane*4);
            acc.x += av*w.x; acc.y += av*w.y; acc.z += av*w.z; acc.w += av*w.w;
        }
        *(float4*)(g_tuser + (size_t)row*H + lane*4) = acc;
    }
}

// ---------------- cleanup: restore zeroed state for next call ----------------
__global__ void k_cleanup() {
    int g = blockIdx.x * blockDim.x + threadIdx.x;
    if (g < NA/4) ((int4*)g_cnt)[g] = make_int4(0,0,0,0);
    if (g == 0) g_arrive = 0;
}

// ---------------- edge scatter-add (small edge sets only) ----------------
__global__ void k_edge_add(const float* __restrict__ src_tab, const int* __restrict__ es,
                           const int* __restrict__ ed, float* __restrict__ dst_tab, int E) {
    int g = blockIdx.x * blockDim.x + threadIdx.x;
    int e = g >> 5;
    if (e >= E) return;
    int lane = g & 31;
    int s = es[e], d = ed[e];
    float4 v = *(const float4*)(src_tab + (size_t)s*H + lane*4);
    red_add_v4(dst_tab + (size_t)d*H + lane*4, v);
}

// ---------------- e0 L1 aggregation: recompute feat per edge ----------------
__global__ __launch_bounds__(128)
void k_agg_feat(const float* __restrict__ xud, const int* __restrict__ nid,
                const float* __restrict__ emb, const float* __restrict__ Wf,
                const float* __restrict__ bf,
                const int* __restrict__ rowptr, const int* __restrict__ csrc,
                float* __restrict__ aggUB) {
    __shared__ float sW[5*H];
    __shared__ float sb[H];
    int u = blockIdx.x;
    int t = threadIdx.x;
    for (int i = t; i < 5*H; i += 128) sW[i] = Wf[i];
    sb[t] = bf[t];
    __syncthreads();
    int beg = rowptr[N_UD + u];
    int end = (u == N_USER-1) ? 2*E_BIG : rowptr[N_UD + u + 1];
    float w0 = sW[0*H+t], w1 = sW[1*H+t], w2 = sW[2*H+t], w3 = sW[3*H+t], w4 = sW[4*H+t];
    float bb = sb[t];
    float acc = 0.f;
    #pragma unroll 2
    for (int e = beg; e < end; ++e) {
        int s = csrc[e];
        int nr = __ldg(nid + s);
        const float* xp = xud + (size_t)s*5;
        float x0 = __ldg(xp), x1 = __ldg(xp+1), x2 = __ldg(xp+2),
              x3 = __ldg(xp+3), x4 = __ldg(xp+4);
        float v = bb + emb[(size_t)nr*H + t]
                + x0*w0 + x1*w1 + x2*w2 + x3*w3 + x4*w4;
        acc += v;
    }
    aggUB[(size_t)u*H + t] = acc;
}

// ---------------- e0 L2 aggregation by gather (relu(hud1)) ----------------
__global__ __launch_bounds__(128)
void k_agg_user(const float* __restrict__ hud, const int* __restrict__ rowptr,
                const int* __restrict__ csrc, float* __restrict__ aggUB) {
    int u = blockIdx.x;
    int tid = threadIdx.x;
    int beg = rowptr[N_UD + u];
    int end = (u == N_USER-1) ? 2*E_BIG : rowptr[N_UD + u + 1];
    float acc = 0.f;
    int e = beg;
    for (; e + 4 <= end; e += 4) {
        int s0 = csrc[e], s1 = csrc[e+1], s2 = csrc[e+2], s3 = csrc[e+3];
        float v0 = fmaxf(hud[(size_t)s0*H + tid], 0.f);
        float v1 = fmaxf(hud[(size_t)s1*H + tid], 0.f);
        float v2 = fmaxf(hud[(size_t)s2*H + tid], 0.f);
        float v3 = fmaxf(hud[(size_t)s3*H + tid], 0.f);
        acc += (v0 + v1) + (v2 + v3);
    }
    for (; e < end; ++e) acc += fmaxf(hud[(size_t)csrc[e]*H + tid], 0.f);
    aggUB[(size_t)u*H + tid] = acc;
}

// ---------------- small GEMM ----------------
__global__ void k_gemm_small(const float* __restrict__ A, const float* __restrict__ W,
                             const float* __restrict__ bias, float* __restrict__ C,
                             int M, int accum, int relu) {
    int g = blockIdx.x * blockDim.x + threadIdx.x;
    int row = g >> 5;
    if (row >= M) return;
    int lane = g & 31;
    const float* a = A + (size_t)row*H;
    float4 acc = make_float4(0.f,0.f,0.f,0.f);
    #pragma unroll 8
    for (int k = 0; k < H; ++k) {
        float av = __ldg(a + k);
        float4 w = *(const float4*)(W + (size_t)k*H + lane*4);
        acc.x += av*w.x; acc.y += av*w.y; acc.z += av*w.z; acc.w += av*w.w;
    }
    if (bias) {
        float4 b = *(const float4*)(bias + lane*4);
        acc.x += b.x; acc.y += b.y; acc.z += b.z; acc.w += b.w;
    }
    float* cp = C + (size_t)row*H + lane*4;
    if (accum) {
        float4 old = *(float4*)cp;
        acc.x += old.x; acc.y += old.y; acc.z += old.z; acc.w += old.w;
    }
    if (relu) { acc.x=fmaxf(acc.x,0.f); acc.y=fmaxf(acc.y,0.f); acc.z=fmaxf(acc.z,0.f); acc.w=fmaxf(acc.w,0.f); }
    *(float4*)cp = acc;
}

// ================= fused big GEMM: A in smem (ldsm), B fragments from global (L1-hot) ==========
// smem = 73.7KB -> 2 CTAs/SM (occupancy fix per R11 ncu evidence)
// MODE 1: A = feat(x_ud,Wf,bf,emb[nid]); C = A@W + b + e1-CSR(tuser)
// MODE 2: A = relu(Ain); C = A@W + b + e1-CSR(tuser); pred = log_softmax(C@Wout + bout)
#define PADB     272
#define SM_BIAS  0          // 512 B
#define SM_EX    512        // 3072 B -> 3584
#define SM_A     4096       // 128*272 = 34816 -> 38912
#define SM_ALO   38912      // 34816 -> 73728
#define SM_STAGE SM_A       // stage (67584 B) overlays A+ALO after MMA
#define TC_SMEM  73728
#define STG_STRIDE 132

template<int MODE>
__global__ __launch_bounds__(256, 2)
void k_fused_mma(const float* __restrict__ bias,
                 const float* __restrict__ tuser, const int* __restrict__ rowptr,
                 const int* __restrict__ csrc, float* __restrict__ C,
                 const float* __restrict__ Ain,
                 const float* __restrict__ xud, const int* __restrict__ nid,
                 const float* __restrict__ emb, const float* __restrict__ Wf,
                 const float* __restrict__ bf,
                 const float* __restrict__ Wout, const float* __restrict__ bout,
                 float* __restrict__ pred, const uint4* __restrict__ Bfh,
                 const uint4* __restrict__ Bfl, int M) {
    extern __shared__ char smem[];
    uint32_t smem_base = smem_to_u32(smem);
    float* sBias = (float*)(smem + SM_BIAS);
    float* sEx   = (float*)(smem + SM_EX);

    int tid  = threadIdx.x;
    int wid  = tid >> 5;
    int lane = tid & 31;
    long blockRow = (long)blockIdx.x * 128;

    if (tid < 128) sBias[tid] = bias[tid];
    if (MODE == 1) {
        for (int i = tid; i < 768; i += 256) sEx[i] = (i < 640) ? Wf[i] : bf[i-640];
    } else {
        if (tid < 256) sEx[tid] = Wout[tid];
    }
    __syncthreads();

    // ---- prologue: build 128x128 A tile, bf16 hi/lo -> smem ----
    {
        int prow  = tid & 127;
        int khalf = tid >> 7;
        long rowReal = blockRow + prow;
        bool rok = rowReal < M;
        long rsrc = rok ? rowReal : (M-1);
        float x0=0,x1=0,x2=0,x3=0,x4=0; long nr = 0;
        if (MODE == 1) {
            nr = nid[rsrc];
            const float* xp = xud + rsrc*5;
            x0=xp[0]; x1=xp[1]; x2=xp[2]; x3=xp[3]; x4=xp[4];
        }
        #pragma unroll
        for (int j = 0; j < 16; ++j) {
            int k = khalf*64 + j*4;
            float4 o;
            if (MODE == 1) {
                float4 e  = *(const float4*)(emb + nr*H + k);
                float4 w0 = *(const float4*)(sEx + 0*H + k);
                float4 w1 = *(const float4*)(sEx + 1*H + k);
                float4 w2 = *(const float4*)(sEx + 2*H + k);
                float4 w3 = *(const float4*)(sEx + 3*H + k);
                float4 w4 = *(const float4*)(sEx + 4*H + k);
                float4 bb = *(const float4*)(sEx + 5*H + k);
                o.x = bb.x + e.x + x0*w0.x + x1*w1.x + x2*w2.x + x3*w3.x + x4*w4.x;
                o.y = bb.y + e.y + x0*w0.y + x1*w1.y + x2*w2.y + x3*w3.y + x4*w4.y;
                o.z = bb.z + e.z + x0*w0.z + x1*w1.z + x2*w2.z + x3*w3.z + x4*w4.z;
                o.w = bb.w + e.w + x0*w0.w + x1*w1.w + x2*w2.w + x3*w3.w + x4*w4.w;
            } else {
                o = *(const float4*)(Ain + rsrc*H + k);
                o.x=fmaxf(o.x,0.f); o.y=fmaxf(o.y,0.f); o.z=fmaxf(o.z,0.f); o.w=fmaxf(o.w,0.f);
            }
            uint32_t h0, h1;
            asm("cvt.rn.bf16x2.f32 %0, %1, %2;" : "=r"(h0) : "f"(o.y), "f"(o.x));
            asm("cvt.rn.bf16x2.f32 %0, %1, %2;" : "=r"(h1) : "f"(o.w), "f"(o.z));
            float hx = __uint_as_float(h0 << 16);
            float hy = __uint_as_float(h0 & 0xffff0000u);
            float hz = __uint_as_float(h1 << 16);
            float hw = __uint_as_float(h1 & 0xffff0000u);
            uint32_t l0, l1;
            asm("cvt.rn.bf16x2.f32 %0, %1, %2;" : "=r"(l0) : "f"(o.y - hy), "f"(o.x - hx));
            asm("cvt.rn.bf16x2.f32 %0, %1, %2;" : "=r"(l1) : "f"(o.w - hw), "f"(o.z - hz));
            uint2 hh; hh.x = h0; hh.y = h1;
            uint2 ll; ll.x = l0; ll.y = l1;
            int off = prow*PADB + k*2;
            *(uint2*)(smem + SM_A   + off) = hh;
            *(uint2*)(smem + SM_ALO + off) = ll;
        }
    }
    __syncthreads();

    // ---- MMA mainloop: warp (wm, wn) owns 32 rows x 64 cols; B from global fragments ----
    int wm = wid & 3, wn = wid >> 2;
    float acc[2][8][4];
    #pragma unroll
    for (int mt = 0; mt < 2; ++mt)
        #pragma unroll
        for (int nt = 0; nt < 8; ++nt)
            #pragma unroll
            for (int q = 0; q < 4; ++q) acc[mt][nt][q] = 0.f;

    #pragma unroll
    for (int kc = 0; kc < 8; ++kc) {
        uint32_t ah[2][4], al[2][4];
        #pragma unroll
        for (int mt = 0; mt < 2; ++mt) {
            int row  = wm*32 + mt*16 + (lane & 15);
            int koff = kc*16 + (lane >> 4)*8;
            uint32_t off = row*PADB + koff*2;
            ldsm_x4(ah[mt], smem_base + SM_A   + off);
            ldsm_x4(al[mt], smem_base + SM_ALO + off);
        }
        #pragma unroll
        for (int g = 0; g < 4; ++g) {
            int gg = wn*4 + g;
            uint4 b4h = __ldg(&Bfh[(gg*8 + kc)*32 + lane]);
            uint4 b4l = __ldg(&Bfl[(gg*8 + kc)*32 + lane]);
            #pragma unroll
            for (int mt = 0; mt < 2; ++mt) {
                mma_bf16(acc[mt][2*g+0], ah[mt], b4h.x, b4h.y);
                mma_bf16(acc[mt][2*g+0], ah[mt], b4l.x, b4l.y);
                mma_bf16(acc[mt][2*g+0], al[mt], b4h.x, b4h.y);
                mma_bf16(acc[mt][2*g+1], ah[mt], b4h.z, b4h.w);
                mma_bf16(acc[mt][2*g+1], ah[mt], b4l.z, b4l.w);
                mma_bf16(acc[mt][2*g+1], al[mt], b4h.z, b4h.w);
            }
        }
    }

    // ---- stage accumulators to smem (overlays A) ----
    __syncthreads();
    float* stage = (float*)(smem + SM_STAGE);
    {
        int g = lane >> 2, t2 = (lane & 3)*2;
        #pragma unroll
        for (int mt = 0; mt < 2; ++mt) {
            #pragma unroll
            for (int nt = 0; nt < 8; ++nt) {
                int r0 = wm*32 + mt*16 + g;
                int c0 = wn*64 + nt*8 + t2;
                *(float2*)(stage + r0*STG_STRIDE + c0)     = make_float2(acc[mt][nt][0], acc[mt][nt][1]);
                *(float2*)(stage + (r0+8)*STG_STRIDE + c0) = make_float2(acc[mt][nt][2], acc[mt][nt][3]);
            }
        }
    }
    __syncthreads();

    // ---- epilogue: 4 threads/row; bias + e1-CSR + store (+pred) ----
    {
        int row = tid >> 2;              // 0..63 -> two row passes
        int q4  = tid & 3;               // 32-col chunk
        #pragma unroll
        for (int pass = 0; pass < 2; ++pass) {
            int lrow = pass*64 + row;
            long orow = blockRow + lrow;
            bool ok = orow < M;
            long rc = ok ? orow : (M-1);
            int beg = rowptr[rc];
            int end = rowptr[rc+1];      // rowptr[N_UD] == E_BIG
            float v[32];
            const float* sp = stage + lrow*STG_STRIDE + q4*32;
            #pragma unroll
            for (int j = 0; j < 8; ++j) {
                float4 t = *(const float4*)(sp + j*4);
                float4 b = *(const float4*)(sBias + q4*32 + j*4);
                v[4*j+0]=t.x+b.x; v[4*j+1]=t.y+b.y; v[4*j+2]=t.z+b.z; v[4*j+3]=t.w+b.w;
            }
            for (int e = beg; e < end; ++e) {
                const float4* tp = (const float4*)(tuser + (size_t)csrc[e]*H + q4*32);
                #pragma unroll
                for (int j = 0; j < 8; ++j) {
                    float4 u = tp[j];
                    v[4*j+0]+=u.x; v[4*j+1]+=u.y; v[4*j+2]+=u.z; v[4*j+3]+=u.w;
                }
            }
            if (ok) {
                float4* cp = (float4*)(C + orow*H + q4*32);
                #pragma unroll
                for (int j = 0; j < 8; ++j)
                    cp[j] = make_float4(v[4*j+0], v[4*j+1], v[4*j+2], v[4*j+3]);
            }
            if (MODE == 2) {
                float z0 = 0.f, z1 = 0.f;
                #pragma unroll
                for (int j = 0; j < 32; ++j) {
                    int col = q4*32 + j;
                    z0 += v[j] * sEx[2*col];
                    z1 += v[j] * sEx[2*col+1];
                }
                z0 += __shfl_xor_sync(0xffffffffu, z0, 1);
                z1 += __shfl_xor_sync(0xffffffffu, z1, 1);
                z0 += __shfl_xor_sync(0xffffffffu, z0, 2);
                z1 += __shfl_xor_sync(0xffffffffu, z1, 2);
                if (q4 == 0 && ok) {
                    z0 += bout[0]; z1 += bout[1];
                    float m = fmaxf(z0, z1);
                    float l = m + logf(expf(z0 - m) + expf(z1 - m));
                    *(float2*)(pred + orow*2) = make_float2(z0 - l, z1 - l);
                }
            }
        }
    }
}

// ---------------- launch ----------------
extern "C" void kernel_launch(void* const* d_in, const int* in_sizes, int n_in,
                              void* d_out, int out_size) {
    const float* x_ud   = (const float*)d_in[0];
    const float* W_feat = (const float*)d_in[1];
    const float* b_feat = (const float*)d_in[2];
    const float* emb_ud = (const float*)d_in[3];
    const float* emb_us = (const float*)d_in[4];
    const float* emb_sp = (const float*)d_in[5];
    const float* Wr1 = (const float*)d_in[6];
    const float* br1 = (const float*)d_in[7];
    const float* Wt1 = (const float*)d_in[8];
    const float* Wr2 = (const float*)d_in[9];
    const float* br2 = (const float*)d_in[10];
    const float* Wt2 = (const float*)d_in[11];
    const float* Wout = (const float*)d_in[12];
    const float* bout = (const float*)d_in[13];
    const int* nid_ud = (const int*)d_in[14];
    const int* nid_us = (const int*)d_in[15];
    const int* nid_sp = (const int*)d_in[16];
    const int* e0s = (const int*)d_in[17];
    const int* e0d = (const int*)d_in[18];
    const int* e1s = (const int*)d_in[19];
    const int* e1d = (const int*)d_in[20];
    const int* e2s = (const int*)d_in[21];
    const int* e2d = (const int*)d_in[22];
    const int* e3s = (const int*)d_in[23];
    const int* e3d = (const int*)d_in[24];

    float *p_hud1, *p_user0, *p_user1, *p_sup0, *p_sup1, *p_tuser, *p_agg;
    int *p_rowptr, *p_csrc;
    uint4 *p_bfh, *p_bfl;
    cudaGetSymbolAddress((void**)&p_hud1,  g_hud1);
    cudaGetSymbolAddress((void**)&p_user0, g_user0);
    cudaGetSymbolAddress((void**)&p_user1, g_user1);
    cudaGetSymbolAddress((void**)&p_sup0,  g_sup0);
    cudaGetSymbolAddress((void**)&p_sup1,  g_sup1);
    cudaGetSymbolAddress((void**)&p_tuser, g_tuser);
    cudaGetSymbolAddress((void**)&p_agg,   g_agg);
    cudaGetSymbolAddress((void**)&p_rowptr, g_rowptr);
    cudaGetSymbolAddress((void**)&p_csrc,   g_csrc);
    cudaGetSymbolAddress((void**)&p_bfh,    g_Bfh);
    cudaGetSymbolAddress((void**)&p_bfl,    g_Bfl);

    float* out    = (float*)d_out;
    float* o_pred = out;
    float* o_hud  = out + 1000000;
    float* o_user = out + 65000000;
    float* o_sup  = out + 65512000;

    cudaFuncSetAttribute(k_fused_mma<1>, cudaFuncAttributeMaxDynamicSharedMemorySize, TC_SMEM);
    cudaFuncSetAttribute(k_fused_mma<2>, cudaFuncAttributeMaxDynamicSharedMemorySize, TC_SMEM);

    const int T = 256;
    int gridUs32  = (N_USER*32 + T-1)/T;
    int gridSp32  = (N_SUP*32 + T-1)/T;
    int gridES    = (E_SMALL*32 + T-1)/T;
    int gridClean = (NA/4 + T-1)/T;

    // ---- L1..L3: merged init (3 launches) ----
    k_combo<<<CB_TOT, T>>>(Wt1, Wt2, emb_us, nid_us, emb_sp, nid_sp, e1d, e0d);
    k_scan1<<<SCAN_BLK, SCAN_T>>>();
    k_fill_tuser<<<FT_F + FT_G, T>>>(e1s, e1d, e0s, e0d, p_user0, Wr1 + 1*HH);

    // ---- L4 (ncu-profiled): fused feat+GEMM+e1 CSR ----
    k_fused_mma<1><<<N_TILES, 256, TC_SMEM>>>(
        br1 + 1*H, p_tuser, p_rowptr, p_csrc, p_hud1,
        nullptr, x_ud, nid_ud, emb_ud, W_feat, b_feat,
        nullptr, nullptr, nullptr, p_bfh, p_bfl, N_UD);

    // ---- layer 1 aggregations ----
    k_agg_feat<<<N_USER, 128>>>(x_ud, nid_ud, emb_ud, W_feat, b_feat,
                                p_rowptr, p_csrc, p_agg + L1_UB);
    k_edge_add<<<gridES, T>>>(p_sup0,  e3s, e3d, p_agg + L1_US, E_SMALL);
    k_edge_add<<<gridES, T>>>(p_user0, e2s, e2d, p_agg + L1_S,  E_SMALL);

    // ---- layer 1 user/sup outputs (post-relu stored) ----
    k_gemm_small<<<gridUs32, T>>>(p_agg + L1_UB, Wr1 + 0*HH, br1 + 0*H, p_user1, N_USER, 0, 0);
    k_gemm_small<<<gridUs32, T>>>(p_agg + L1_US, Wr1 + 3*HH, br1 + 3*H, p_user1, N_USER, 1, 0);
    k_gemm_small<<<gridUs32, T>>>(p_user0,       Wt1 + 0*HH, nullptr,   p_user1, N_USER, 1, 0);
    k_gemm_small<<<gridUs32, T>>>(p_user0,       Wt1 + 3*HH, nullptr,   p_user1, N_USER, 1, 1);
    k_gemm_small<<<gridSp32, T>>>(p_agg + L1_S,  Wr1 + 2*HH, br1 + 2*H, p_sup1,  N_SUP,  0, 0);
    k_gemm_small<<<gridSp32, T>>>(p_sup0,        Wt1 + 2*HH, nullptr,   p_sup1,  N_SUP,  1, 1);

    // ---- layer 2: tuser2, fused relu+GEMM+e1 CSR+pred ----
    k_gemm_small<<<gridUs32, T>>>(p_user1, Wr2 + 1*HH, nullptr, p_tuser, N_USER, 0, 0);
    k_fused_mma<2><<<N_TILES, 256, TC_SMEM>>>(
        br2 + 1*H, p_tuser, p_rowptr, p_csrc, o_hud,
        p_hud1, nullptr, nullptr, nullptr, nullptr, nullptr,
        Wout, bout, o_pred, p_bfh + 2048, p_bfl + 2048, N_UD);

    // ---- layer 2 aggregations + user/sup outputs ----
    k_agg_user<<<N_USER, 128>>>(p_hud1, p_rowptr, p_csrc, p_agg + L2_UB);
    k_edge_add<<<gridES, T>>>(p_sup1,  e3s, e3d, p_agg + L2_US, E_SMALL);
    k_edge_add<<<gridES, T>>>(p_user1, e2s, e2d, p_agg + L2_S,  E_SMALL);
    k_gemm_small<<<gridUs32, T>>>(p_agg + L2_UB, Wr2 + 0*HH, br2 + 0*H, o_user, N_USER, 0, 0);
    k_gemm_small<<<gridUs32, T>>>(p_agg + L2_US, Wr2 + 3*HH, br2 + 3*H, o_user, N_USER, 1, 0);
    k_gemm_small<<<gridUs32, T>>>(p_user1,       Wt2 + 0*HH, nullptr,   o_user, N_USER, 1, 0);
    k_gemm_small<<<gridUs32, T>>>(p_user1,       Wt2 + 3*HH, nullptr,   o_user, N_USER, 1, 0);
    k_gemm_small<<<gridSp32, T>>>(p_agg + L2_S,  Wr2 + 2*HH, br2 + 2*H, o_sup,  N_SUP,  0, 0);
    k_gemm_small<<<gridSp32, T>>>(p_sup1,        Wt2 + 2*HH, nullptr,   o_sup,  N_SUP,  1, 0);

    // ---- cleanup: restore zeroed counters/flags for next deterministic call ----
    k_cleanup<<<gridClean, T>>>();

    (void)in_sizes; (void)n_in; (void)out_size;
}

// round 13
// speedup vs baseline: 1.4156x; 1.2276x over previous
#include <cuda_runtime.h>
#include <cuda_bf16.h>
#include <math.h>
#include <cstdint>

#define N_UD   500000
#define N_USER 4000
#define N_SUP  300
#define H      128
#define HH     (H*H)
#define E_BIG  500000
#define E_SMALL 4000
#define SZ_U   (N_USER*H)
#define SZ_S   (N_SUP*H)
#define NA     (N_UD + N_USER)   // combined CSR key space
#define N_TILES 3907             // ceil(N_UD/128)

// ---------------- scratch (static __device__ -> no allocations) ----------------
__device__ __align__(16) float g_hud1[(size_t)N_UD*H];
__device__ __align__(16) float g_user0[SZ_U];
__device__ __align__(16) float g_user1[SZ_U];
__device__ __align__(16) float g_sup0[SZ_S];
__device__ __align__(16) float g_sup1[SZ_S];
__device__ __align__(16) float g_tuser[SZ_U];

// fragment-ordered bf16-split weights for the two big GEMMs (mma B operand layout)
__device__ __align__(16) uint4 g_Bfh[2*2048];
__device__ __align__(16) uint4 g_Bfl[2*2048];

// combined CSR: keys [0,N_UD) = e1 by dst (vals = e1 src user)
//               keys [N_UD,NA) = e0 by dst user (vals = e0 src UD)
__device__ int g_cnt[NA];       // zeroed statically + by k_cleanup each call
__device__ int g_rowptr[NA];
__device__ int g_pos[NA];
__device__ int g_csrc[2*E_BIG];

// single-pass scan scratch
#define SCAN_T    1024
#define SCAN_IT   4
#define SCAN_BLK  124            // ceil(NA / 4096)
__device__ int g_bsum[SCAN_BLK];
__device__ int g_arrive;         // zeroed statically + by k_cleanup

#define AGG_TOT (2*(2*SZ_U+SZ_S))
__device__ __align__(16) float g_agg[AGG_TOT];
#define L1_UB 0
#define L1_US (SZ_U)
#define L1_S  (2*SZ_U)
#define L2_UB (2*SZ_U+SZ_S)
#define L2_US (L2_UB+SZ_U)
#define L2_S  (L2_UB+2*SZ_U)

// ---------------- helpers ----------------
__device__ __forceinline__ uint32_t smem_to_u32(const void* p) {
    uint32_t a;
    asm("{ .reg .u64 t; cvta.to.shared.u64 t, %1; cvt.u32.u64 %0, t; }" : "=r"(a) : "l"(p));
    return a;
}
__device__ __forceinline__ void red_add_v4(float* p, float4 v) {
    asm volatile("red.global.add.v4.f32 [%0], {%1,%2,%3,%4};"
                 :: "l"(p), "f"(v.x), "f"(v.y), "f"(v.z), "f"(v.w) : "memory");
}
__device__ __forceinline__ void ldsm_x4(uint32_t* r, uint32_t addr) {
    asm volatile("ldmatrix.sync.aligned.m8n8.x4.shared.b16 {%0,%1,%2,%3}, [%4];"
        : "=r"(r[0]), "=r"(r[1]), "=r"(r[2]), "=r"(r[3]) : "r"(addr));
}
__device__ __forceinline__ void mma_bf16(float* d, const uint32_t* a, uint32_t b0, uint32_t b1) {
    asm volatile("mma.sync.aligned.m16n8k16.row.col.f32.bf16.bf16.f32 "
        "{%0,%1,%2,%3}, {%4,%5,%6,%7}, {%8,%9}, {%0,%1,%2,%3};"
        : "+f"(d[0]), "+f"(d[1]), "+f"(d[2]), "+f"(d[3])
        : "r"(a[0]), "r"(a[1]), "r"(a[2]), "r"(a[3]), "r"(b0), "r"(b1));
}

// ================= L1 combo: zero agg | prepW(frag) | gathers | hist =================
#define CB_Z   2075
#define CB_P   128
#define CB_G1  500
#define CB_G2  38
#define CB_H   1954
#define CB_TOT (CB_Z + CB_P + CB_G1 + CB_G2 + CB_H)

__global__ __launch_bounds__(256)
void k_combo(const float* __restrict__ Wt1, const float* __restrict__ Wt2,
             const float* __restrict__ emb_us, const int* __restrict__ nid_us,
             const float* __restrict__ emb_sp, const int* __restrict__ nid_sp,
             const int* __restrict__ e1d, const int* __restrict__ e0d) {
    int b = blockIdx.x, t = threadIdx.x;
    if (b < CB_Z) {
        int g = b*256 + t;
        if (g < AGG_TOT/4) ((float4*)g_agg)[g] = make_float4(0.f,0.f,0.f,0.f);
    } else if (b < CB_Z + CB_P) {
        int i = (b - CB_Z)*256 + t;      // i < 2*HH
        int w = i >> 14;
        int r = i & (HH-1);
        int n = r >> 7, k = r & 127;
        const float* W = (w ? Wt2 : Wt1) + HH;   // Wt_1 (UD root)
        float v = W[k*H + n];                     // B[n][k] = W[k][n]
        __nv_bfloat16 hi = __float2bfloat16(v);
        __nv_bfloat16 lo = __float2bfloat16(v - __bfloat162float(hi));
        int g16 = n >> 4, kc = k >> 4;
        int m = (((n >> 3) & 1) << 1) | ((k >> 3) & 1);
        int lane = ((n & 7) << 2) | ((k & 7) >> 1);
        int base = (((w*64 + g16*8 + kc)*32 + lane) << 2) | m;
        ((__nv_bfloat16*)g_Bfh)[base*2 + (k & 1)] = hi;
        ((__nv_bfloat16*)g_Bfl)[base*2 + (k & 1)] = lo;
    } else if (b < CB_Z + CB_P + CB_G1) {
        int g = (b - CB_Z - CB_P)*256 + t;
        int row = g >> 5, lane = g & 31;
        int r = nid_us[row];
        float4 v = *(const float4*)(emb_us + (size_t)r*H + lane*4);
        *(float4*)(g_user0 + (size_t)row*H + lane*4) = v;
    } else if (b < CB_Z + CB_P + CB_G1 + CB_G2) {
        int g = (b - CB_Z - CB_P - CB_G1)*256 + t;
        int row = g >> 5, lane = g & 31;
        if (row < N_SUP) {
            int r = nid_sp[row];
            float4 v = *(const float4*)(emb_sp + (size_t)r*H + lane*4);
            *(float4*)(g_sup0 + (size_t)row*H + lane*4) = v;
        }
    } else {
        int e = (b - CB_Z - CB_P - CB_G1 - CB_G2)*256 + t;
        if (e < E_BIG) {
            atomicAdd(&g_cnt[e1d[e]], 1);
            atomicAdd(&g_cnt[N_UD + e0d[e]], 1);
        }
    }
}

// ================= L2: single-kernel exclusive scan over g_cnt[NA] =================
__global__ __launch_bounds__(SCAN_T)
void k_scan1() {
    __shared__ int s[SCAN_T];
    __shared__ int sboff;
    int b = blockIdx.x, t = threadIdx.x;
    int base = b*(SCAN_T*SCAN_IT) + t*SCAN_IT;
    int v[SCAN_IT];
    #pragma unroll
    for (int i = 0; i < SCAN_IT; ++i) {
        int idx = base + i;
        v[i] = (idx < NA) ? g_cnt[idx] : 0;
    }
    int ts = v[0] + v[1] + v[2] + v[3];
    s[t] = ts; __syncthreads();
    #pragma unroll
    for (int o = 1; o < SCAN_T; o <<= 1) {
        int x = (t >= o) ? s[t-o] : 0;
        __syncthreads(); s[t] += x; __syncthreads();
    }
    int texcl = s[t] - ts;
    if (t == 0) {
        g_bsum[b] = s[SCAN_T-1];
        __threadfence();
        atomicAdd(&g_arrive, 1);
        while (atomicAdd(&g_arrive, 0) < gridDim.x) { }
        int sum = 0;
        for (int i = 0; i < b; ++i) sum += g_bsum[i];
        sboff = sum;
    }
    __syncthreads();
    int off = sboff + texcl;
    #pragma unroll
    for (int i = 0; i < SCAN_IT; ++i) {
        int idx = base + i;
        if (idx < NA) { g_rowptr[idx] = off; g_pos[idx] = off; }
        off += v[i];
    }
}

// ================= L3: CSR fill + tuser GEMM combined =================
#define FT_F   1954
#define FT_G   500
__global__ __launch_bounds__(256)
void k_fill_tuser(const int* __restrict__ e1s, const int* __restrict__ e1d,
                  const int* __restrict__ e0s, const int* __restrict__ e0d,
                  const float* __restrict__ A, const float* __restrict__ W) {
    int b = blockIdx.x, t = threadIdx.x;
    if (b < FT_F) {
        int e = b*256 + t;
        if (e < E_BIG) {
            int p = atomicAdd(&g_pos[e1d[e]], 1);
            g_csrc[p] = e1s[e];
            int q = atomicAdd(&g_pos[N_UD + e0d[e]], 1);
            g_csrc[q] = e0s[e];
        }
    } else {
        int g = (b - FT_F)*256 + t;
        int row = g >> 5, lane = g & 31;
        const float* a = A + (size_t)row*H;
        float4 acc = make_float4(0.f,0.f,0.f,0.f);
        #pragma unroll 8
        for (int k = 0; k < H; ++k) {
            float av = __ldg(a + k);
            float4 w = *(const float4*)(W + (size_t)k*H + lane*4);
            acc.x += av*w.x; acc.y += av*w.y; acc.z += av*w.z; acc.w += av*w.w;
        }
        *(float4*)(g_tuser + (size_t)row*H + lane*4) = acc;
    }
}

// ---------------- cleanup: restore zeroed state for next call ----------------
__global__ void k_cleanup() {
    int g = blockIdx.x * blockDim.x + threadIdx.x;
    if (g < NA/4) ((int4*)g_cnt)[g] = make_int4(0,0,0,0);
    if (g == 0) g_arrive = 0;
}

// ---------------- edge scatter-add (small edge sets only) ----------------
__global__ void k_edge_add(const float* __restrict__ src_tab, const int* __restrict__ es,
                           const int* __restrict__ ed, float* __restrict__ dst_tab, int E) {
    int g = blockIdx.x * blockDim.x + threadIdx.x;
    int e = g >> 5;
    if (e >= E) return;
    int lane = g & 31;
    int s = es[e], d = ed[e];
    float4 v = *(const float4*)(src_tab + (size_t)s*H + lane*4);
    red_add_v4(dst_tab + (size_t)d*H + lane*4, v);
}

// ---------------- e0 L1 aggregation: recompute feat per edge ----------------
__global__ __launch_bounds__(128)
void k_agg_feat(const float* __restrict__ xud, const int* __restrict__ nid,
                const float* __restrict__ emb, const float* __restrict__ Wf,
                const float* __restrict__ bf,
                const int* __restrict__ rowptr, const int* __restrict__ csrc,
                float* __restrict__ aggUB) {
    __shared__ float sW[5*H];
    __shared__ float sb[H];
    int u = blockIdx.x;
    int t = threadIdx.x;
    for (int i = t; i < 5*H; i += 128) sW[i] = Wf[i];
    sb[t] = bf[t];
    __syncthreads();
    int beg = rowptr[N_UD + u];
    int end = (u == N_USER-1) ? 2*E_BIG : rowptr[N_UD + u + 1];
    float w0 = sW[0*H+t], w1 = sW[1*H+t], w2 = sW[2*H+t], w3 = sW[3*H+t], w4 = sW[4*H+t];
    float bb = sb[t];
    float acc = 0.f;
    #pragma unroll 2
    for (int e = beg; e < end; ++e) {
        int s = csrc[e];
        int nr = __ldg(nid + s);
        const float* xp = xud + (size_t)s*5;
        float x0 = __ldg(xp), x1 = __ldg(xp+1), x2 = __ldg(xp+2),
              x3 = __ldg(xp+3), x4 = __ldg(xp+4);
        float v = bb + emb[(size_t)nr*H + t]
                + x0*w0 + x1*w1 + x2*w2 + x3*w3 + x4*w4;
        acc += v;
    }
    aggUB[(size_t)u*H + t] = acc;
}

// ---------------- e0 L2 aggregation by gather (relu(hud1)) ----------------
__global__ __launch_bounds__(128)
void k_agg_user(const float* __restrict__ hud, const int* __restrict__ rowptr,
                const int* __restrict__ csrc, float* __restrict__ aggUB) {
    int u = blockIdx.x;
    int tid = threadIdx.x;
    int beg = rowptr[N_UD + u];
    int end = (u == N_USER-1) ? 2*E_BIG : rowptr[N_UD + u + 1];
    float acc = 0.f;
    int e = beg;
    for (; e + 4 <= end; e += 4) {
        int s0 = csrc[e], s1 = csrc[e+1], s2 = csrc[e+2], s3 = csrc[e+3];
        float v0 = fmaxf(hud[(size_t)s0*H + tid], 0.f);
        float v1 = fmaxf(hud[(size_t)s1*H + tid], 0.f);
        float v2 = fmaxf(hud[(size_t)s2*H + tid], 0.f);
        float v3 = fmaxf(hud[(size_t)s3*H + tid], 0.f);
        acc += (v0 + v1) + (v2 + v3);
    }
    for (; e < end; ++e) acc += fmaxf(hud[(size_t)csrc[e]*H + tid], 0.f);
    aggUB[(size_t)u*H + tid] = acc;
}

// ---------------- small GEMM ----------------
__global__ void k_gemm_small(const float* __restrict__ A, const float* __restrict__ W,
                             const float* __restrict__ bias, float* __restrict__ C,
                             int M, int accum, int relu) {
    int g = blockIdx.x * blockDim.x + threadIdx.x;
    int row = g >> 5;
    if (row >= M) return;
    int lane = g & 31;
    const float* a = A + (size_t)row*H;
    float4 acc = make_float4(0.f,0.f,0.f,0.f);
    #pragma unroll 8
    for (int k = 0; k < H; ++k) {
        float av = __ldg(a + k);
        float4 w = *(const float4*)(W + (size_t)k*H + lane*4);
        acc.x += av*w.x; acc.y += av*w.y; acc.z += av*w.z; acc.w += av*w.w;
    }
    if (bias) {
        float4 b = *(const float4*)(bias + lane*4);
        acc.x += b.x; acc.y += b.y; acc.z += b.z; acc.w += b.w;
    }
    float* cp = C + (size_t)row*H + lane*4;
    if (accum) {
        float4 old = *(float4*)cp;
        acc.x += old.x; acc.y += old.y; acc.z += old.z; acc.w += old.w;
    }
    if (relu) { acc.x=fmaxf(acc.x,0.f); acc.y=fmaxf(acc.y,0.f); acc.z=fmaxf(acc.z,0.f); acc.w=fmaxf(acc.w,0.f); }
    *(float4*)cp = acc;
}

// ================= fused big GEMM: coalesced row-per-warp prologue/epilogue ==========
// smem = 73.7KB -> 2 CTAs/SM; B fragments from global (L1-hot)
// MODE 1: A = feat(x_ud,Wf,bf,emb[nid]); C = A@W + b + e1-CSR(tuser)
// MODE 2: A = relu(Ain); C = A@W + b + e1-CSR(tuser); pred = log_softmax(C@Wout + bout)
#define PADB     272
#define SM_BIAS  0
#define SM_EX    512
#define SM_A     4096
#define SM_ALO   38912
#define SM_STAGE SM_A
#define TC_SMEM  73728
#define STG_STRIDE 132

template<int MODE>
__global__ __launch_bounds__(256, 2)
void k_fused_mma(const float* __restrict__ bias,
                 const float* __restrict__ tuser, const int* __restrict__ rowptr,
                 const int* __restrict__ csrc, float* __restrict__ C,
                 const float* __restrict__ Ain,
                 const float* __restrict__ xud, const int* __restrict__ nid,
                 const float* __restrict__ emb, const float* __restrict__ Wf,
                 const float* __restrict__ bf,
                 const float* __restrict__ Wout, const float* __restrict__ bout,
                 float* __restrict__ pred, const uint4* __restrict__ Bfh,
                 const uint4* __restrict__ Bfl, int M) {
    extern __shared__ char smem[];
    uint32_t smem_base = smem_to_u32(smem);
    float* sBias = (float*)(smem + SM_BIAS);
    float* sEx   = (float*)(smem + SM_EX);

    int tid  = threadIdx.x;
    int wid  = tid >> 5;
    int lane = tid & 31;
    long blockRow = (long)blockIdx.x * 128;

    if (tid < 128) sBias[tid] = bias[tid];
    if (MODE == 1) {
        for (int i = tid; i < 768; i += 256) sEx[i] = (i < 640) ? Wf[i] : bf[i-640];
    } else {
        if (tid < 256) sEx[tid] = Wout[tid];
    }
    __syncthreads();

    // ---- prologue: row-per-warp, coalesced; each warp builds 16 rows ----
    {
        int kcol = lane*4;   // this lane's 4 columns (fixed)
        float4 we0, we1, we2, we3, we4, web;
        if (MODE == 1) {
            we0 = *(const float4*)(sEx + 0*H + kcol);
            we1 = *(const float4*)(sEx + 1*H + kcol);
            we2 = *(const float4*)(sEx + 2*H + kcol);
            we3 = *(const float4*)(sEx + 3*H + kcol);
            we4 = *(const float4*)(sEx + 4*H + kcol);
            web = *(const float4*)(sEx + 5*H + kcol);
        }
        #pragma unroll 4
        for (int i = 0; i < 16; ++i) {
            int prow = wid*16 + i;
            long rowReal = blockRow + prow;
            long rsrc = (rowReal < M) ? rowReal : (M-1);
            float4 o;
            if (MODE == 1) {
                long nr = __ldg(nid + rsrc);
                const float* xp = xud + rsrc*5;
                float x0 = __ldg(xp), x1 = __ldg(xp+1), x2 = __ldg(xp+2),
                      x3 = __ldg(xp+3), x4 = __ldg(xp+4);
                float4 e = *(const float4*)(emb + nr*H + kcol);
                o.x = web.x + e.x + x0*we0.x + x1*we1.x + x2*we2.x + x3*we3.x + x4*we4.x;
                o.y = web.y + e.y + x0*we0.y + x1*we1.y + x2*we2.y + x3*we3.y + x4*we4.y;
                o.z = web.z + e.z + x0*we0.z + x1*we1.z + x2*we2.z + x3*we3.z + x4*we4.z;
                o.w = web.w + e.w + x0*we0.w + x1*we1.w + x2*we2.w + x3*we3.w + x4*we4.w;
            } else {
                o = *(const float4*)(Ain + rsrc*H + kcol);
                o.x=fmaxf(o.x,0.f); o.y=fmaxf(o.y,0.f); o.z=fmaxf(o.z,0.f); o.w=fmaxf(o.w,0.f);
            }
            uint32_t h0, h1;
            asm("cvt.rn.bf16x2.f32 %0, %1, %2;" : "=r"(h0) : "f"(o.y), "f"(o.x));
            asm("cvt.rn.bf16x2.f32 %0, %1, %2;" : "=r"(h1) : "f"(o.w), "f"(o.z));
            float hx = __uint_as_float(h0 << 16);
            float hy = __uint_as_float(h0 & 0xffff0000u);
            float hz = __uint_as_float(h1 << 16);
            float hw = __uint_as_float(h1 & 0xffff0000u);
            uint32_t l0, l1;
            asm("cvt.rn.bf16x2.f32 %0, %1, %2;" : "=r"(l0) : "f"(o.y - hy), "f"(o.x - hx));
            asm("cvt.rn.bf16x2.f32 %0, %1, %2;" : "=r"(l1) : "f"(o.w - hw), "f"(o.z - hz));
            uint2 hh; hh.x = h0; hh.y = h1;
            uint2 ll; ll.x = l0; ll.y = l1;
            int off = prow*PADB + kcol*2;
            *(uint2*)(smem + SM_A   + off) = hh;
            *(uint2*)(smem + SM_ALO + off) = ll;
        }
    }
    __syncthreads();

    // ---- MMA mainloop: warp (wm, wn) owns 32 rows x 64 cols; B from global fragments ----
    int wm = wid & 3, wn = wid >> 2;
    float acc[2][8][4];
    #pragma unroll
    for (int mt = 0; mt < 2; ++mt)
        #pragma unroll
        for (int nt = 0; nt < 8; ++nt)
            #pragma unroll
            for (int q = 0; q < 4; ++q) acc[mt][nt][q] = 0.f;

    #pragma unroll
    for (int kc = 0; kc < 8; ++kc) {
        uint32_t ah[2][4], al[2][4];
        #pragma unroll
        for (int mt = 0; mt < 2; ++mt) {
            int row  = wm*32 + mt*16 + (lane & 15);
            int koff = kc*16 + (lane >> 4)*8;
            uint32_t off = row*PADB + koff*2;
            ldsm_x4(ah[mt], smem_base + SM_A   + off);
            ldsm_x4(al[mt], smem_base + SM_ALO + off);
        }
        #pragma unroll
        for (int g = 0; g < 4; ++g) {
            int gg = wn*4 + g;
            uint4 b4h = __ldg(&Bfh[(gg*8 + kc)*32 + lane]);
            uint4 b4l = __ldg(&Bfl[(gg*8 + kc)*32 + lane]);
            #pragma unroll
            for (int mt = 0; mt < 2; ++mt) {
                mma_bf16(acc[mt][2*g+0], ah[mt], b4h.x, b4h.y);
                mma_bf16(acc[mt][2*g+0], ah[mt], b4l.x, b4l.y);
                mma_bf16(acc[mt][2*g+0], al[mt], b4h.x, b4h.y);
                mma_bf16(acc[mt][2*g+1], ah[mt], b4h.z, b4h.w);
                mma_bf16(acc[mt][2*g+1], ah[mt], b4l.z, b4l.w);
                mma_bf16(acc[mt][2*g+1], al[mt], b4h.z, b4h.w);
            }
        }
    }

    // ---- stage accumulators to smem (overlays A) ----
    __syncthreads();
    float* stage = (float*)(smem + SM_STAGE);
    {
        int g = lane >> 2, t2 = (lane & 3)*2;
        #pragma unroll
        for (int mt = 0; mt < 2; ++mt) {
            #pragma unroll
            for (int nt = 0; nt < 8; ++nt) {
                int r0 = wm*32 + mt*16 + g;
                int c0 = wn*64 + nt*8 + t2;
                *(float2*)(stage + r0*STG_STRIDE + c0)     = make_float2(acc[mt][nt][0], acc[mt][nt][1]);
                *(float2*)(stage + (r0+8)*STG_STRIDE + c0) = make_float2(acc[mt][nt][2], acc[mt][nt][3]);
            }
        }
    }
    __syncthreads();

    // ---- epilogue: row-per-warp, coalesced; bias + e1-CSR + store (+pred) ----
    {
        int kcol = lane*4;
        float4 b4 = *(const float4*)(sBias + kcol);
        float4 wa = make_float4(0,0,0,0), wb = make_float4(0,0,0,0);
        float bo0 = 0.f, bo1 = 0.f;
        if (MODE == 2) {
            wa = *(const float4*)(sEx + 2*kcol);       // {w[c0].0, w[c0].1, w[c1].0, w[c1].1}
            wb = *(const float4*)(sEx + 2*kcol + 4);   // {w[c2].0, w[c2].1, w[c3].0, w[c3].1}
            bo0 = bout[0]; bo1 = bout[1];
        }
        #pragma unroll 2
        for (int i = 0; i < 16; ++i) {
            int lrow = wid*16 + i;
            long orow = blockRow + lrow;
            bool ok = orow < M;
            long rc = ok ? orow : (M-1);
            int beg = __ldg(rowptr + rc);
            int end = __ldg(rowptr + rc + 1);    // rowptr[N_UD] == E_BIG
            float4 t4 = *(const float4*)(stage + lrow*STG_STRIDE + kcol);
            float4 v = make_float4(t4.x + b4.x, t4.y + b4.y, t4.z + b4.z, t4.w + b4.w);
            for (int e = beg; e < end; ++e) {
                float4 u = *(const float4*)(tuser + (size_t)csrc[e]*H + kcol);
                v.x += u.x; v.y += u.y; v.z += u.z; v.w += u.w;
            }
            if (ok) *(float4*)(C + orow*H + kcol) = v;
            if (MODE == 2) {
                float z0 = v.x*wa.x + v.y*wa.z + v.z*wb.x + v.w*wb.z;
                float z1 = v.x*wa.y + v.y*wa.w + v.z*wb.y + v.w*wb.w;
                #pragma unroll
                for (int o = 16; o > 0; o >>= 1) {
                    z0 += __shfl_xor_sync(0xffffffffu, z0, o);
                    z1 += __shfl_xor_sync(0xffffffffu, z1, o);
                }
                if (lane == 0 && ok) {
                    z0 += bo0; z1 += bo1;
                    float m = fmaxf(z0, z1);
                    float l = m + logf(expf(z0 - m) + expf(z1 - m));
                    *(float2*)(pred + orow*2) = make_float2(z0 - l, z1 - l);
                }
            }
        }
    }
}

// ---------------- launch ----------------
extern "C" void kernel_launch(void* const* d_in, const int* in_sizes, int n_in,
                              void* d_out, int out_size) {
    const float* x_ud   = (const float*)d_in[0];
    const float* W_feat = (const float*)d_in[1];
    const float* b_feat = (const float*)d_in[2];
    const float* emb_ud = (const float*)d_in[3];
    const float* emb_us = (const float*)d_in[4];
    const float* emb_sp = (const float*)d_in[5];
    const float* Wr1 = (const float*)d_in[6];
    const float* br1 = (const float*)d_in[7];
    const float* Wt1 = (const float*)d_in[8];
    const float* Wr2 = (const float*)d_in[9];
    const float* br2 = (const float*)d_in[10];
    const float* Wt2 = (const float*)d_in[11];
    const float* Wout = (const float*)d_in[12];
    const float* bout = (const float*)d_in[13];
    const int* nid_ud = (const int*)d_in[14];
    const int* nid_us = (const int*)d_in[15];
    const int* nid_sp = (const int*)d_in[16];
    const int* e0s = (const int*)d_in[17];
    const int* e0d = (const int*)d_in[18];
    const int* e1s = (const int*)d_in[19];
    const int* e1d = (const int*)d_in[20];
    const int* e2s = (const int*)d_in[21];
    const int* e2d = (const int*)d_in[22];
    const int* e3s = (const int*)d_in[23];
    const int* e3d = (const int*)d_in[24];

    float *p_hud1, *p_user0, *p_user1, *p_sup0, *p_sup1, *p_tuser, *p_agg;
    int *p_rowptr, *p_csrc;
    uint4 *p_bfh, *p_bfl;
    cudaGetSymbolAddress((void**)&p_hud1,  g_hud1);
    cudaGetSymbolAddress((void**)&p_user0, g_user0);
    cudaGetSymbolAddress((void**)&p_user1, g_user1);
    cudaGetSymbolAddress((void**)&p_sup0,  g_sup0);
    cudaGetSymbolAddress((void**)&p_sup1,  g_sup1);
    cudaGetSymbolAddress((void**)&p_tuser, g_tuser);
    cudaGetSymbolAddress((void**)&p_agg,   g_agg);
    cudaGetSymbolAddress((void**)&p_rowptr, g_rowptr);
    cudaGetSymbolAddress((void**)&p_csrc,   g_csrc);
    cudaGetSymbolAddress((void**)&p_bfh,    g_Bfh);
    cudaGetSymbolAddress((void**)&p_bfl,    g_Bfl);

    float* out    = (float*)d_out;
    float* o_pred = out;
    float* o_hud  = out + 1000000;
    float* o_user = out + 65000000;
    float* o_sup  = out + 65512000;

    cudaFuncSetAttribute(k_fused_mma<1>, cudaFuncAttributeMaxDynamicSharedMemorySize, TC_SMEM);
    cudaFuncSetAttribute(k_fused_mma<2>, cudaFuncAttributeMaxDynamicSharedMemorySize, TC_SMEM);

    const int T = 256;
    int gridUs32  = (N_USER*32 + T-1)/T;
    int gridSp32  = (N_SUP*32 + T-1)/T;
    int gridES    = (E_SMALL*32 + T-1)/T;
    int gridClean = (NA/4 + T-1)/T;

    // ---- L1..L3: merged init (3 launches) ----
    k_combo<<<CB_TOT, T>>>(Wt1, Wt2, emb_us, nid_us, emb_sp, nid_sp, e1d, e0d);
    k_scan1<<<SCAN_BLK, SCAN_T>>>();
    k_fill_tuser<<<FT_F + FT_G, T>>>(e1s, e1d, e0s, e0d, p_user0, Wr1 + 1*HH);

    // ---- L4 (ncu-profiled): fused feat+GEMM+e1 CSR ----
    k_fused_mma<1><<<N_TILES, 256, TC_SMEM>>>(
        br1 + 1*H, p_tuser, p_rowptr, p_csrc, p_hud1,
        nullptr, x_ud, nid_ud, emb_ud, W_feat, b_feat,
        nullptr, nullptr, nullptr, p_bfh, p_bfl, N_UD);

    // ---- layer 1 aggregations ----
    k_agg_feat<<<N_USER, 128>>>(x_ud, nid_ud, emb_ud, W_feat, b_feat,
                                p_rowptr, p_csrc, p_agg + L1_UB);
    k_edge_add<<<gridES, T>>>(p_sup0,  e3s, e3d, p_agg + L1_US, E_SMALL);
    k_edge_add<<<gridES, T>>>(p_user0, e2s, e2d, p_agg + L1_S,  E_SMALL);

    // ---- layer 1 user/sup outputs (post-relu stored) ----
    k_gemm_small<<<gridUs32, T>>>(p_agg + L1_UB, Wr1 + 0*HH, br1 + 0*H, p_user1, N_USER, 0, 0);
    k_gemm_small<<<gridUs32, T>>>(p_agg + L1_US, Wr1 + 3*HH, br1 + 3*H, p_user1, N_USER, 1, 0);
    k_gemm_small<<<gridUs32, T>>>(p_user0,       Wt1 + 0*HH, nullptr,   p_user1, N_USER, 1, 0);
    k_gemm_small<<<gridUs32, T>>>(p_user0,       Wt1 + 3*HH, nullptr,   p_user1, N_USER, 1, 1);
    k_gemm_small<<<gridSp32, T>>>(p_agg + L1_S,  Wr1 + 2*HH, br1 + 2*H, p_sup1,  N_SUP,  0, 0);
    k_gemm_small<<<gridSp32, T>>>(p_sup0,        Wt1 + 2*HH, nullptr,   p_sup1,  N_SUP,  1, 1);

    // ---- layer 2: tuser2, fused relu+GEMM+e1 CSR+pred ----
    k_gemm_small<<<gridUs32, T>>>(p_user1, Wr2 + 1*HH, nullptr, p_tuser, N_USER, 0, 0);
    k_fused_mma<2><<<N_TILES, 256, TC_SMEM>>>(
        br2 + 1*H, p_tuser, p_rowptr, p_csrc, o_hud,
        p_hud1, nullptr, nullptr, nullptr, nullptr, nullptr,
        Wout, bout, o_pred, p_bfh + 2048, p_bfl + 2048, N_UD);

    // ---- layer 2 aggregations + user/sup outputs ----
    k_agg_user<<<N_USER, 128>>>(p_hud1, p_rowptr, p_csrc, p_agg + L2_UB);
    k_edge_add<<<gridES, T>>>(p_sup1,  e3s, e3d, p_agg + L2_US, E_SMALL);
    k_edge_add<<<gridES, T>>>(p_user1, e2s, e2d, p_agg + L2_S,  E_SMALL);
    k_gemm_small<<<gridUs32, T>>>(p_agg + L2_UB, Wr2 + 0*HH, br2 + 0*H, o_user, N_USER, 0, 0);
    k_gemm_small<<<gridUs32, T>>>(p_agg + L2_US, Wr2 + 3*HH, br2 + 3*H, o_user, N_USER, 1, 0);
    k_gemm_small<<<gridUs32, T>>>(p_user1,       Wt2 + 0*HH, nullptr,   o_user, N_USER, 1, 0);
    k_gemm_small<<<gridUs32, T>>>(p_user1,       Wt2 + 3*HH, nullptr,   o_user, N_USER, 1, 0);
    k_gemm_small<<<gridSp32, T>>>(p_agg + L2_S,  Wr2 + 2*HH, br2 + 2*H, o_sup,  N_SUP,  0, 0);
    k_gemm_small<<<gridSp32, T>>>(p_sup1,        Wt2 + 2*HH, nullptr,   o_sup,  N_SUP,  1, 0);

    // ---- cleanup ----
    k_cleanup<<<gridClean, T>>>();

    (void)in_sizes; (void)n_in; (void)out_size;
}